// round 10
// baseline (speedup 1.0000x reference)
#include <cuda_runtime.h>
#include <math.h>
#include <stdint.h>

#define AD 1024
#define BD 16384
#define DD 768
#define TEMPC 100.0f
#define EPSC 1e-8f
#define NONDIFF 30
#define DIFFST 10
#define NBLK 256            /* BD / 64 column blocks */
#define ENTCAP 8192

// ---- device scratch (allocation-free: __device__ globals) ----
__device__ float g_anorm[AD * DD];
__device__ float g_X[AD * AD];
__device__ float g_Xp[AD * AD];              // fragment-order tf32 X
__device__ float g_rsx[AD];
__device__ float g_q[AD * BD];
__device__ float g_c[AD * BD];
__device__ float g_grad[AD * BD];
__device__ float g_sm[AD * BD];
__device__ float g_smTp[(size_t)BD * AD];    // fragment-order tf32 softmax (B operand)
__device__ float g_xsm[AD * BD];
__device__ float g_ynorm[BD];
__device__ float g_invyn[BD];
__device__ int   g_amin[AD];
__device__ float g_num[BD];
__device__ float g_den[BD];
__device__ float g_denpart[NBLK];
__device__ unsigned long long g_minp[AD * NBLK];
// sparse nondiff state
__device__ float g_alpha[BD];
__device__ float g_lam[BD];
__device__ float g_colq[BD];
__device__ float g_colg[BD];
__device__ int   g_ej[NONDIFF * AD];
__device__ float g_ew[NONDIFF * AD];

__device__ __forceinline__ float tf32_rna(float x) {
    float r;
    asm("cvt.rna.tf32.f32 %0, %1;" : "=f"(r) : "f"(x));
    return r;
}
__device__ __forceinline__ uint32_t smem_u32(const void* p) {
    uint32_t a;
    asm("{ .reg .u64 t; cvta.to.shared.u64 t, %1; cvt.u32.u64 %0, t; }" : "=r"(a) : "l"(p));
    return a;
}
__device__ __forceinline__ unsigned fenc(float v) {
    unsigned b = __float_as_uint(v);
    return b ^ ((b & 0x80000000u) ? 0xFFFFFFFFu : 0x80000000u);
}
__device__ __forceinline__ unsigned long long packmin(float v, int j) {
    return ((unsigned long long)fenc(v) << 32) | (unsigned)j;
}
#define CP16(dst, src) asm volatile("cp.async.cg.shared.global [%0], [%1], 16;" :: "r"(dst), "l"(src))
#define CP_COMMIT()    asm volatile("cp.async.commit_group;" ::: "memory")
#define CP_WAIT(n)     asm volatile("cp.async.wait_group %0;" :: "n"(n) : "memory")

__device__ __forceinline__ void mma_tf32_16n8k8(float* c, const uint32_t* a, const uint32_t* b) {
    asm volatile(
        "mma.sync.aligned.m16n8k8.row.col.f32.tf32.tf32.f32 "
        "{%0,%1,%2,%3}, {%4,%5,%6,%7}, {%8,%9}, {%0,%1,%2,%3};"
        : "+f"(c[0]), "+f"(c[1]), "+f"(c[2]), "+f"(c[3])
        : "r"(a[0]), "r"(a[1]), "r"(a[2]), "r"(a[3]), "r"(b[0]), "r"(b[1]));
}

// =====================================================================
// staging: compact entries whose column lies in [j0, j0+64) into smem.
// vals[idx] = column; atom = idx & 1023. Deterministic order (idx asc).
// =====================================================================
template <bool WITHW>
__device__ __forceinline__ int stage_win(
    const int* __restrict__ vals, const float* __restrict__ ws, int n, int j0,
    unsigned short* sp, float* sw, int* warp_aux, int cap)
{
    const int tid = threadIdx.x;
    const int w = tid >> 5, lane = tid & 31;
    const int chunk = (n + 7) >> 3;
    const int beg = w * chunk;
    const int end = min(n, beg + chunk);
    int cnt = 0;
    for (int base = beg; base < end; base += 32) {
        int idx = base + lane;
        bool m = false;
        if (idx < end) {
            m = ((unsigned)(vals[idx] - j0) < 64u);
            if (WITHW) m = m && (ws[idx] != 0.0f);
        }
        cnt += __popc(__ballot_sync(0xffffffffu, m));
    }
    if (lane == 0) warp_aux[w] = cnt;
    __syncthreads();
    int base_off = 0, total = 0;
#pragma unroll
    for (int i = 0; i < 8; i++) {
        if (i < w) base_off += warp_aux[i];
        total += warp_aux[i];
    }
    int pos = base_off;
    for (int base = beg; base < end; base += 32) {
        int idx = base + lane;
        int j = (idx < end) ? vals[idx] : -1;
        bool m = (idx < end) && ((unsigned)(j - j0) < 64u);
        if (WITHW && m) m = (ws[idx] != 0.0f);
        unsigned mk = __ballot_sync(0xffffffffu, m);
        if (m) {
            int p = pos + __popc(mk & ((1u << lane) - 1u));
            if (p < cap) {
                sp[p] = (unsigned short)(((j - j0) << 10) | (idx & 1023));
                if (WITHW) sw[p] = ws[idx];
            }
        }
        pos += __popc(mk);
    }
    __syncthreads();
    return min(total, cap);
}

// =====================================================================
// init kernels
// =====================================================================
__global__ void ynorm_kernel(const float* __restrict__ y) {
    int w = (blockIdx.x * blockDim.x + threadIdx.x) >> 5;
    int lane = threadIdx.x & 31;
    if (w >= BD) return;
    const float* row = y + (size_t)w * DD;
    float s = 0.f;
    for (int d = lane; d < DD; d += 32) s += fabsf(row[d]);
#pragma unroll
    for (int o = 16; o; o >>= 1) s += __shfl_xor_sync(0xffffffffu, s, o);
    if (!lane) { g_ynorm[w] = s; g_invyn[w] = 1.0f / s; }
}

__global__ void anorm_kernel(const float* __restrict__ atoms) {
    int r = blockIdx.x;
    const float* row = atoms + (size_t)r * DD;
    __shared__ float red[256];
    float s = 0.f;
    for (int d = threadIdx.x; d < DD; d += 256) s += fabsf(row[d]);
    red[threadIdx.x] = s;
    __syncthreads();
    for (int o = 128; o; o >>= 1) {
        if (threadIdx.x < o) red[threadIdx.x] += red[threadIdx.x + o];
        __syncthreads();
    }
    float nrm = red[0];
    for (int d = threadIdx.x; d < DD; d += 256)
        g_anorm[r * DD + d] = row[d] / nrm;
}

__global__ void rowsumX_kernel() {
    int w = (blockIdx.x * blockDim.x + threadIdx.x) >> 5;
    int lane = threadIdx.x & 31;
    if (w >= AD) return;
    float s = 0.f;
    for (int k = lane; k < AD; k += 32) s += g_X[w * AD + k];
#pragma unroll
    for (int o = 16; o; o >>= 1) s += __shfl_xor_sync(0xffffffffu, s, o);
    if (!lane) g_rsx[w] = s;
}

__global__ void xperm_kernel() {
    int idx = blockIdx.x * 256 + threadIdx.x;
    int L = idx & 31, kt = (idx >> 5) & 127, mt = idx >> 12;
    int r = mt * 16 + (L >> 2), c = kt * 8 + (L & 3);
    float4 v;
    v.x = tf32_rna(g_X[r * AD + c]);
    v.y = tf32_rna(g_X[(r + 8) * AD + c]);
    v.z = tf32_rna(g_X[r * AD + c + 4]);
    v.w = tf32_rna(g_X[(r + 8) * AD + c + 4]);
    *reinterpret_cast<float4*>(g_Xp + (size_t)idx * 4) = v;
}

__global__ void colq_alpha_kernel() {
    int j = blockIdx.x * 256 + threadIdx.x;
    float s = 0.f;
    for (int a = 0; a < AD; a++) s += g_q[(size_t)a * BD + j];
    g_colq[j] = s;
    g_alpha[j] = 1.0f;
}

// =====================================================================
// fp32 SIMT GEMM (X, q, recon)
// =====================================================================
template <bool AKM, bool BKM, int SCALE>
__global__ void __launch_bounds__(256) gemm_kernel(
    const float* __restrict__ A, const float* __restrict__ B, float* __restrict__ C,
    int M, int N, int K, int lda, int ldb, int ldc, const float* __restrict__ scale)
{
    __shared__ float As[16][132];
    __shared__ float Bs[16][132];
    const int tid = threadIdx.x;
    const int tx = tid & 15, ty = tid >> 4;
    const int m0 = blockIdx.y * 128, n0 = blockIdx.x * 128;
    float acc[8][8];
#pragma unroll
    for (int i = 0; i < 8; i++)
#pragma unroll
        for (int j = 0; j < 8; j++) acc[i][j] = 0.f;

    for (int k0 = 0; k0 < K; k0 += 16) {
#pragma unroll
        for (int i = 0; i < 2; i++) {
            int lin = tid + i * 256;
            if (AKM) {
                int kk = lin >> 5, mm = (lin & 31) << 2;
                float4 v = *reinterpret_cast<const float4*>(A + (size_t)(k0 + kk) * lda + (m0 + mm));
                *reinterpret_cast<float4*>(&As[kk][mm]) = v;
            } else {
                int mm = lin >> 2, kk = (lin & 3) << 2;
                float4 v = *reinterpret_cast<const float4*>(A + (size_t)(m0 + mm) * lda + (k0 + kk));
                As[kk + 0][mm] = v.x; As[kk + 1][mm] = v.y;
                As[kk + 2][mm] = v.z; As[kk + 3][mm] = v.w;
            }
        }
#pragma unroll
        for (int i = 0; i < 2; i++) {
            int lin = tid + i * 256;
            if (BKM) {
                int kk = lin >> 5, nn = (lin & 31) << 2;
                float4 v = *reinterpret_cast<const float4*>(B + (size_t)(k0 + kk) * ldb + (n0 + nn));
                *reinterpret_cast<float4*>(&Bs[kk][nn]) = v;
            } else {
                int nn = lin >> 2, kk = (lin & 3) << 2;
                float4 v = *reinterpret_cast<const float4*>(B + (size_t)(n0 + nn) * ldb + (k0 + kk));
                Bs[kk + 0][nn] = v.x; Bs[kk + 1][nn] = v.y;
                Bs[kk + 2][nn] = v.z; Bs[kk + 3][nn] = v.w;
            }
        }
        __syncthreads();
#pragma unroll
        for (int k = 0; k < 16; k++) {
            float af[8], bf[8];
            *reinterpret_cast<float4*>(&af[0]) = *reinterpret_cast<float4*>(&As[k][ty * 8]);
            *reinterpret_cast<float4*>(&af[4]) = *reinterpret_cast<float4*>(&As[k][ty * 8 + 4]);
            *reinterpret_cast<float4*>(&bf[0]) = *reinterpret_cast<float4*>(&Bs[k][tx * 8]);
            *reinterpret_cast<float4*>(&bf[4]) = *reinterpret_cast<float4*>(&Bs[k][tx * 8 + 4]);
#pragma unroll
            for (int i = 0; i < 8; i++)
#pragma unroll
                for (int j = 0; j < 8; j++) acc[i][j] += af[i] * bf[j];
        }
        __syncthreads();
    }
#pragma unroll
    for (int i = 0; i < 8; i++) {
        int m = m0 + ty * 8 + i;
        float rowf = (SCALE == 2) ? scale[m] : 1.f;
#pragma unroll
        for (int j = 0; j < 8; j++) {
            float f = (SCALE == 1) ? scale[n0 + tx * 8 + j] : rowf;
            C[(size_t)m * ldc + n0 + tx * 8 + j] = acc[i][j] * f;
        }
    }
}

// =====================================================================
// xsm = X @ sm via raw mma.sync tf32 (unchanged from R9)
// =====================================================================
#define A_CH 16384
#define B_CH 16384
#define SMEM_DYN (2 * (A_CH + B_CH))

__global__ void __launch_bounds__(256, 2) xsm_mma_kernel() {
    extern __shared__ char smc[];
    const uint32_t sb = smem_u32(smc);
    const int tid = threadIdx.x;
    const int wid = tid >> 5, lane = tid & 31;
    const int m0 = blockIdx.y * 128, n0 = blockIdx.x * 128;
    const int mt0 = m0 >> 4;
    const int nt0 = n0 >> 3;

    float acc[2][8][4];
#pragma unroll
    for (int i = 0; i < 2; i++)
#pragma unroll
        for (int j = 0; j < 8; j++)
#pragma unroll
            for (int v = 0; v < 4; v++) acc[i][j][v] = 0.f;

#define PREFETCH(CK, BUF) do { \
    const int _kt0 = (CK) * 4; \
    _Pragma("unroll") \
    for (int s = 0; s < 4; s++) { \
        int idx = tid + s * 256; \
        int mtl = idx >> 7, remA = idx & 127; \
        const float* srcA = g_Xp + (((size_t)(mt0 + mtl) * 128 + _kt0) * 32) * 4 + remA * 4; \
        CP16(sb + (BUF) * (A_CH + B_CH) + (mtl * 128 + remA) * 16, srcA); \
        int ntl = idx >> 6, remB = idx & 63; \
        const float* srcB = g_smTp + (((size_t)(nt0 + ntl) * 128 + _kt0) * 32) * 2 + remB * 4; \
        CP16(sb + (BUF) * (A_CH + B_CH) + A_CH + (ntl * 64 + remB) * 16, srcB); \
    } \
    CP_COMMIT(); } while (0)

    PREFETCH(0, 0);

    const int wm = (wid >> 1) * 2;
    const int wn = (wid & 1) * 8;

    const int NCK = AD / 32;
    for (int ck = 0; ck < NCK; ck++) {
        const int buf = ck & 1;
        if (ck + 1 < NCK) {
            PREFETCH(ck + 1, (ck + 1) & 1);
            CP_WAIT(1);
        } else {
            CP_WAIT(0);
        }
        __syncthreads();

        const char* Abase = smc + buf * (A_CH + B_CH);
        const char* Bbase = Abase + A_CH;

#pragma unroll
        for (int ktl = 0; ktl < 4; ktl++) {
            uint32_t afr[2][4];
#pragma unroll
            for (int i = 0; i < 2; i++) {
                uint4 v = *reinterpret_cast<const uint4*>(
                    Abase + (((wm + i) * 4 + ktl) * 32 + lane) * 16);
                afr[i][0] = v.x; afr[i][1] = v.y; afr[i][2] = v.z; afr[i][3] = v.w;
            }
            uint32_t bfr[8][2];
#pragma unroll
            for (int j = 0; j < 8; j++) {
                uint2 v = *reinterpret_cast<const uint2*>(
                    Bbase + (((wn + j) * 4 + ktl) * 32 + lane) * 8);
                bfr[j][0] = v.x; bfr[j][1] = v.y;
            }
#pragma unroll
            for (int i = 0; i < 2; i++)
#pragma unroll
                for (int j = 0; j < 8; j++)
                    mma_tf32_16n8k8(acc[i][j], afr[i], bfr[j]);
        }
        __syncthreads();
    }
#undef PREFETCH

    const int grp = lane >> 2, q4 = lane & 3;
#pragma unroll
    for (int i = 0; i < 2; i++) {
        int row = m0 + (wid >> 1) * 32 + i * 16 + grp;
#pragma unroll
        for (int j = 0; j < 8; j++) {
            int col = n0 + (wid & 1) * 64 + j * 8 + q4 * 2;
            *reinterpret_cast<float2*>(g_xsm + (size_t)row * BD + col) =
                make_float2(acc[i][j][0], acc[i][j][1]);
            *reinterpret_cast<float2*>(g_xsm + (size_t)(row + 8) * BD + col) =
                make_float2(acc[i][j][2], acc[i][j][3]);
        }
    }
}

// =====================================================================
// sparse nondiff: per-step dense pass over q computing grad on the fly
//   grad[a][j] = alpha_j*rsx[a]/A - q[a][j] + sum_e w_e X[a][a_e]
// emits: colg[j], per-(a,block) argmin partials
// =====================================================================
__global__ void __launch_bounds__(256) nds_pass_kernel(int t) {
    extern __shared__ char dsm[];
    float* se_w = reinterpret_cast<float*>(dsm);
    unsigned short* se_p = reinterpret_cast<unsigned short*>(dsm + ENTCAP * 4);
    __shared__ int warp_aux[8];
    __shared__ float s_alpha[64];
    __shared__ float4 rn[16][17];
    const int tid = threadIdx.x, tx = tid & 15, ty = tid >> 4;
    const int j0 = blockIdx.x * 64, jb = j0 + tx * 4;
    if (tid < 64) s_alpha[tid] = g_alpha[j0 + tid];
    __syncthreads();
    int ns = 0;
    if (t > 0) ns = stage_win<true>(g_ej, g_ew, t * 1024, j0, se_p, se_w, warp_aux, ENTCAP);

    const float4 alpha4 = make_float4(s_alpha[tx*4], s_alpha[tx*4+1], s_alpha[tx*4+2], s_alpha[tx*4+3]);
    float4 colg = {0, 0, 0, 0};
    for (int a = ty; a < AD; a += 16) {
        const float rA = g_rsx[a] * (1.0f / AD);
        float4 q4 = *reinterpret_cast<const float4*>(g_q + (size_t)a * BD + jb);
        float4 corr = {0, 0, 0, 0};
        for (int e = 0; e < ns; e++) {
            int p = se_p[e];
            int d = (p >> 10) - tx * 4;
            if ((unsigned)d < 4u) {
                float xv = se_w[e] * g_X[a * AD + (p & 1023)];
                corr.x += (d == 0) ? xv : 0.f;
                corr.y += (d == 1) ? xv : 0.f;
                corr.z += (d == 2) ? xv : 0.f;
                corr.w += (d == 3) ? xv : 0.f;
            }
        }
        float4 g4;
        g4.x = alpha4.x * rA - q4.x + corr.x;
        g4.y = alpha4.y * rA - q4.y + corr.y;
        g4.z = alpha4.z * rA - q4.z + corr.z;
        g4.w = alpha4.w * rA - q4.w + corr.w;
        colg.x += g4.x; colg.y += g4.y; colg.z += g4.z; colg.w += g4.w;

        unsigned long long best = packmin(g4.x, jb);
        unsigned long long k1 = packmin(g4.y, jb + 1);
        unsigned long long k2 = packmin(g4.z, jb + 2);
        unsigned long long k3 = packmin(g4.w, jb + 3);
        if (k1 < best) best = k1;
        if (k2 < best) best = k2;
        if (k3 < best) best = k3;
#pragma unroll
        for (int o = 8; o; o >>= 1) {
            unsigned long long v = __shfl_down_sync(0xffffffffu, best, o, 16);
            if (v < best) best = v;
        }
        if (tx == 0) g_minp[(size_t)a * NBLK + blockIdx.x] = best;
    }
    rn[ty][tx] = colg;
    __syncthreads();
    if (ty == 0) {
        float4 n = rn[0][tx];
        for (int q = 1; q < 16; q++) {
            float4 n2 = rn[q][tx];
            n.x += n2.x; n.y += n2.y; n.z += n2.z; n.w += n2.w;
        }
        *reinterpret_cast<float4*>(g_colg + jb) = n;
    }
}

__global__ void __launch_bounds__(256) argmin_parts_kernel() {
    const int wid = threadIdx.x >> 5, lane = threadIdx.x & 31;
    const int a = blockIdx.x * 8 + wid;
    unsigned long long best = ~0ull;
#pragma unroll
    for (int k = 0; k < NBLK / 32; k++) {
        unsigned long long v = g_minp[(size_t)a * NBLK + lane + k * 32];
        if (v < best) best = v;
    }
#pragma unroll
    for (int o = 16; o; o >>= 1) {
        unsigned long long v = __shfl_down_sync(0xffffffffu, best, o);
        if (v < best) best = v;
    }
    if (!lane) g_amin[a] = (int)(best & 0xFFFFFFFFu);
}

// per-column num_j / den_j from sparse terms (4 threads per column)
__global__ void __launch_bounds__(256) nds_lamden_kernel(int t) {
    extern __shared__ char dsm[];
    float* se_w = reinterpret_cast<float*>(dsm);
    unsigned short* se_p = reinterpret_cast<unsigned short*>(dsm + ENTCAP * 4);
    __shared__ int warp_aux[8];
    __shared__ unsigned short sn_p[1024];
    __shared__ float s_alpha[64];
    const int tid = threadIdx.x;
    const int j0 = blockIdx.x * 64;
    if (tid < 64) s_alpha[tid] = g_alpha[j0 + tid];
    __syncthreads();
    int ns = 0;
    if (t > 0) ns = stage_win<true>(g_ej, g_ew, t * 1024, j0, se_p, se_w, warp_aux, ENTCAP);
    int nnew = stage_win<false>(g_amin, nullptr, 1024, j0, sn_p, nullptr, warp_aux, 1024);

    const int col = tid >> 2, sub = tid & 3;
    const int j = j0 + col;
    const float alpha = s_alpha[col], alphaA = alpha * (1.0f / AD);
    float s_new_g = 0, s_new_q = 0, s_new_rsx = 0, T1 = 0;
    float s_old_g = 0, s_old_q = 0, T2old = 0;

    for (int i = sub; i < nnew; i += 4) {
        int p = sn_p[i];
        if ((p >> 10) != col) continue;
        int a = p & 1023;
        float qv = g_q[(size_t)a * BD + j];
        float corr = 0;
        for (int e = 0; e < ns; e++) {
            int p2 = se_p[e];
            if ((p2 >> 10) == col) corr += se_w[e] * g_X[a * AD + (p2 & 1023)];
        }
        float ga = alpha * g_rsx[a] * (1.0f / AD) - qv + corr;
        s_new_g += ga; s_new_q += qv; s_new_rsx += g_rsx[a];
        float sc = 0;
        for (int i2 = 0; i2 < nnew; i2++) {
            int p3 = sn_p[i2];
            if ((p3 >> 10) == col) sc += g_X[a * AD + (p3 & 1023)];
        }
        T1 += sc;
    }
    for (int e = sub; e < ns; e += 4) {
        int p = se_p[e];
        if ((p >> 10) != col) continue;
        int ae = p & 1023;
        float w = se_w[e];
        float qv = g_q[(size_t)ae * BD + j];
        float corr = 0;
        for (int e2 = 0; e2 < ns; e2++) {
            int p2 = se_p[e2];
            if ((p2 >> 10) == col) corr += se_w[e2] * g_X[ae * AD + (p2 & 1023)];
        }
        float ge = alpha * g_rsx[ae] * (1.0f / AD) - qv + corr;
        s_old_g += w * ge; s_old_q += w * qv;
        float sc = 0;
        for (int i2 = 0; i2 < nnew; i2++) {
            int p3 = sn_p[i2];
            if ((p3 >> 10) == col) sc += g_X[ae * AD + (p3 & 1023)];
        }
        T2old += w * sc;
    }
#pragma unroll
    for (int o = 2; o; o >>= 1) {
        s_new_g  += __shfl_down_sync(0xffffffffu, s_new_g,  o, 4);
        s_new_q  += __shfl_down_sync(0xffffffffu, s_new_q,  o, 4);
        s_new_rsx+= __shfl_down_sync(0xffffffffu, s_new_rsx,o, 4);
        T1       += __shfl_down_sync(0xffffffffu, T1,       o, 4);
        s_old_g  += __shfl_down_sync(0xffffffffu, s_old_g,  o, 4);
        s_old_q  += __shfl_down_sync(0xffffffffu, s_old_q,  o, 4);
        T2old    += __shfl_down_sync(0xffffffffu, T2old,    o, 4);
    }
    if (sub == 0) {
        float num = s_new_g - (alphaA * g_colg[j] + s_old_g);
        float T2 = alphaA * s_new_rsx + T2old;
        float T56 = s_new_q - (alphaA * g_colq[j] + s_old_q);
        g_num[j] = num;
        g_den[j] = (T1 - T2) - num - T56;
    }
}

// every block computes the SAME deterministic denom, then lam/alpha for 256 cols
__global__ void __launch_bounds__(256) nds_lamalpha_kernel() {
    __shared__ float red[256];
    const int tid = threadIdx.x;
    float s = 0.f;
    for (int i = 0; i < 64; i++) s += g_den[tid * 64 + i];
    red[tid] = s;
    __syncthreads();
    for (int o = 128; o; o >>= 1) {
        if (tid < o) red[tid] += red[tid + o];
        __syncthreads();
    }
    const float denom = red[0] + EPSC;
    int j = blockIdx.x * 256 + tid;
    float lam = fminf(fmaxf(-g_num[j] / denom, 0.f), 1.f);
    g_lam[j] = lam;
    g_alpha[j] *= (1.f - lam);
}

__global__ void nds_entryupd_kernel(int t) {
    int idx = blockIdx.x * 256 + threadIdx.x;
    if (idx >= (t + 1) * 1024) return;
    int s = idx >> 10;
    if (s < t) {
        g_ew[idx] *= (1.f - g_lam[g_ej[idx]]);
    } else {
        int a = idx & 1023;
        int j = g_amin[a];
        g_ej[idx] = j;
        g_ew[idx] = g_lam[j];
    }
}

// materialize c and grad for the diff phase
__global__ void __launch_bounds__(256) nds_finalize_kernel() {
    extern __shared__ char dsm[];
    float* se_w = reinterpret_cast<float*>(dsm);
    unsigned short* se_p = reinterpret_cast<unsigned short*>(dsm + ENTCAP * 4);
    __shared__ int warp_aux[8];
    __shared__ float s_alpha[64];
    const int tid = threadIdx.x, tx = tid & 15, ty = tid >> 4;
    const int j0 = blockIdx.x * 64, jb = j0 + tx * 4;
    if (tid < 64) s_alpha[tid] = g_alpha[j0 + tid];
    __syncthreads();
    int ns = stage_win<true>(g_ej, g_ew, NONDIFF * 1024, j0, se_p, se_w, warp_aux, ENTCAP);

    const float4 alpha4 = make_float4(s_alpha[tx*4], s_alpha[tx*4+1], s_alpha[tx*4+2], s_alpha[tx*4+3]);
    const float4 alphaA4 = make_float4(alpha4.x * (1.0f/AD), alpha4.y * (1.0f/AD),
                                       alpha4.z * (1.0f/AD), alpha4.w * (1.0f/AD));
    for (int a = ty; a < AD; a += 16) {
        const float rA = g_rsx[a] * (1.0f / AD);
        float4 q4 = *reinterpret_cast<const float4*>(g_q + (size_t)a * BD + jb);
        float4 corr = {0, 0, 0, 0}, cadd = {0, 0, 0, 0};
        for (int e = 0; e < ns; e++) {
            int p = se_p[e];
            int d = (p >> 10) - tx * 4;
            if ((unsigned)d < 4u) {
                int ae = p & 1023;
                float w = se_w[e];
                float xv = w * g_X[a * AD + ae];
                corr.x += (d == 0) ? xv : 0.f;
                corr.y += (d == 1) ? xv : 0.f;
                corr.z += (d == 2) ? xv : 0.f;
                corr.w += (d == 3) ? xv : 0.f;
                if (ae == a) {
                    cadd.x += (d == 0) ? w : 0.f;
                    cadd.y += (d == 1) ? w : 0.f;
                    cadd.z += (d == 2) ? w : 0.f;
                    cadd.w += (d == 3) ? w : 0.f;
                }
            }
        }
        float4 c4, g4;
        c4.x = alphaA4.x + cadd.x; c4.y = alphaA4.y + cadd.y;
        c4.z = alphaA4.z + cadd.z; c4.w = alphaA4.w + cadd.w;
        g4.x = alpha4.x * rA - q4.x + corr.x;
        g4.y = alpha4.y * rA - q4.y + corr.y;
        g4.z = alpha4.z * rA - q4.z + corr.z;
        g4.w = alpha4.w * rA - q4.w + corr.w;
        *reinterpret_cast<float4*>(g_c + (size_t)a * BD + jb) = c4;
        *reinterpret_cast<float4*>(g_grad + (size_t)a * BD + jb) = g4;
    }
}

// =====================================================================
// diff phase (unchanged from R9)
// =====================================================================
__global__ void __launch_bounds__(256) softmaxT_kernel() {
    const int tid = threadIdx.x, tx = tid & 15, ty = tid >> 4;
    const int j0 = blockIdx.x * 64, jb = j0 + tx * 4;

    float4 m4 = {-INFINITY, -INFINITY, -INFINITY, -INFINITY};
    float4 s4 = {0, 0, 0, 0};
    for (int a = ty; a < AD; a += 16) {
        float4 g = *reinterpret_cast<const float4*>(g_grad + (size_t)a * BD + jb);
        float v;
        v = -TEMPC * g.x; if (v > m4.x) { s4.x = s4.x * expf(m4.x - v) + 1.f; m4.x = v; } else s4.x += expf(v - m4.x);
        v = -TEMPC * g.y; if (v > m4.y) { s4.y = s4.y * expf(m4.y - v) + 1.f; m4.y = v; } else s4.y += expf(v - m4.y);
        v = -TEMPC * g.z; if (v > m4.z) { s4.z = s4.z * expf(m4.z - v) + 1.f; m4.z = v; } else s4.z += expf(v - m4.z);
        v = -TEMPC * g.w; if (v > m4.w) { s4.w = s4.w * expf(m4.w - v) + 1.f; m4.w = v; } else s4.w += expf(v - m4.w);
    }
    __shared__ float4 mm[16][17], ss[16][17];
    __shared__ float4 fm[16], fsinv[16];
    mm[ty][tx] = m4; ss[ty][tx] = s4;
    __syncthreads();
    if (ty == 0) {
        float4 M = mm[0][tx], S = ss[0][tx];
        for (int t = 1; t < 16; t++) {
            float4 m2 = mm[t][tx], s2 = ss[t][tx];
            float Mn;
            Mn = fmaxf(M.x, m2.x); S.x = S.x * expf(M.x - Mn) + s2.x * expf(m2.x - Mn); M.x = Mn;
            Mn = fmaxf(M.y, m2.y); S.y = S.y * expf(M.y - Mn) + s2.y * expf(m2.y - Mn); M.y = Mn;
            Mn = fmaxf(M.z, m2.z); S.z = S.z * expf(M.z - Mn) + s2.z * expf(m2.z - Mn); M.z = Mn;
            Mn = fmaxf(M.w, m2.w); S.w = S.w * expf(M.w - Mn) + s2.w * expf(m2.w - Mn); M.w = Mn;
        }
        fm[tx] = M;
        fsinv[tx] = make_float4(1.f / S.x, 1.f / S.y, 1.f / S.z, 1.f / S.w);
    }
    __syncthreads();
    const float4 M4 = fm[tx];
    const float4 I4 = fsinv[tx];

    __shared__ float tile[32][68];
    const int L = tid & 31, nt = tid >> 5;
    for (int at = 0; at < 32; at++) {
        const int a0 = at * 32;
#pragma unroll
        for (int half = 0; half < 2; half++) {
            int aa = ty + half * 16;
            size_t idx = (size_t)(a0 + aa) * BD + jb;
            float4 g = *reinterpret_cast<const float4*>(g_grad + idx);
            float4 e;
            e.x = expf(-TEMPC * g.x - M4.x) * I4.x;
            e.y = expf(-TEMPC * g.y - M4.y) * I4.y;
            e.z = expf(-TEMPC * g.z - M4.z) * I4.z;
            e.w = expf(-TEMPC * g.w - M4.w) * I4.w;
            *reinterpret_cast<float4*>(g_sm + idx) = e;
            tile[aa][tx * 4 + 0] = e.x;
            tile[aa][tx * 4 + 1] = e.y;
            tile[aa][tx * 4 + 2] = e.z;
            tile[aa][tx * 4 + 3] = e.w;
        }
        __syncthreads();
#pragma unroll
        for (int kt = 0; kt < 4; kt++) {
            float v0 = tile[kt * 8 + (L & 3)][nt * 8 + (L >> 2)];
            float v1 = tile[kt * 8 + (L & 3) + 4][nt * 8 + (L >> 2)];
            size_t o = (((size_t)(j0 / 8 + nt) * 128 + (at * 4 + kt)) * 32 + L) * 2;
            *reinterpret_cast<float2*>(g_smTp + o) =
                make_float2(tf32_rna(v0), tf32_rna(v1));
        }
        __syncthreads();
    }
}

__global__ void __launch_bounds__(256) d_reduce_kernel() {
    const int tid = threadIdx.x, tx = tid & 15, ty = tid >> 4;
    const int jb = blockIdx.x * 64 + tx * 4;
    float4 num4 = {0, 0, 0, 0}, den4 = {0, 0, 0, 0};
    for (int a = ty; a < AD; a += 16) {
        size_t idx = (size_t)a * BD + jb;
        float4 sm = *reinterpret_cast<const float4*>(g_sm + idx);
        float4 cc = *reinterpret_cast<const float4*>(g_c + idx);
        float4 xs = *reinterpret_cast<const float4*>(g_xsm + idx);
        float4 gg = *reinterpret_cast<const float4*>(g_grad + idx);
        float4 qq = *reinterpret_cast<const float4*>(g_q + idx);
        float4 dd, xd;
        dd.x = sm.x - cc.x; dd.y = sm.y - cc.y; dd.z = sm.z - cc.z; dd.w = sm.w - cc.w;
        xd.x = xs.x - gg.x - qq.x; xd.y = xs.y - gg.y - qq.y;
        xd.z = xs.z - gg.z - qq.z; xd.w = xs.w - gg.w - qq.w;
        num4.x += dd.x * gg.x; num4.y += dd.y * gg.y;
        num4.z += dd.z * gg.z; num4.w += dd.w * gg.w;
        den4.x += dd.x * xd.x; den4.y += dd.y * xd.y;
        den4.z += dd.z * xd.z; den4.w += dd.w * xd.w;
    }
    __shared__ float4 rn[16][17], rd[16][17];
    __shared__ float colden[16];
    rn[ty][tx] = num4; rd[ty][tx] = den4;
    __syncthreads();
    if (ty == 0) {
        float4 n = rn[0][tx], d = rd[0][tx];
        for (int t = 1; t < 16; t++) {
            float4 n2 = rn[t][tx], d2 = rd[t][tx];
            n.x += n2.x; n.y += n2.y; n.z += n2.z; n.w += n2.w;
            d.x += d2.x; d.y += d2.y; d.z += d2.z; d.w += d2.w;
        }
        *reinterpret_cast<float4*>(g_num + jb) = n;
        colden[tx] = d.x + d.y + d.z + d.w;
    }
    __syncthreads();
    if (tid == 0) {
        float s = 0.f;
        for (int t = 0; t < 16; t++) s += colden[t];
        g_denpart[blockIdx.x] = s;
    }
}

template <bool LAST>
__global__ void __launch_bounds__(256) d_update_kernel() {
    const int tid = threadIdx.x, tx = tid & 15, ty = tid >> 4;
    const int jb = blockIdx.x * 64 + tx * 4;
    __shared__ float red[256];
    red[tid] = g_denpart[tid];
    __syncthreads();
    for (int o = 128; o; o >>= 1) {
        if (tid < o) red[tid] += red[tid + o];
        __syncthreads();
    }
    const float denom = red[0] + EPSC;
    float4 nm = *reinterpret_cast<const float4*>(g_num + jb);
    float4 lam;
    lam.x = fminf(fmaxf(-nm.x / denom, 0.f), 1.f);
    lam.y = fminf(fmaxf(-nm.y / denom, 0.f), 1.f);
    lam.z = fminf(fmaxf(-nm.z / denom, 0.f), 1.f);
    lam.w = fminf(fmaxf(-nm.w / denom, 0.f), 1.f);
    for (int a = ty; a < AD; a += 16) {
        size_t idx = (size_t)a * BD + jb;
        float4 sm = *reinterpret_cast<const float4*>(g_sm + idx);
        float4 cc = *reinterpret_cast<const float4*>(g_c + idx);
        float4 c2;
        c2.x = cc.x + lam.x * (sm.x - cc.x);
        c2.y = cc.y + lam.y * (sm.y - cc.y);
        c2.z = cc.z + lam.z * (sm.z - cc.z);
        c2.w = cc.w + lam.w * (sm.w - cc.w);
        *reinterpret_cast<float4*>(g_c + idx) = c2;
        if (!LAST) {
            float4 xs = *reinterpret_cast<const float4*>(g_xsm + idx);
            float4 gg = *reinterpret_cast<const float4*>(g_grad + idx);
            float4 qq = *reinterpret_cast<const float4*>(g_q + idx);
            float4 g2;
            g2.x = gg.x + lam.x * (xs.x - gg.x - qq.x);
            g2.y = gg.y + lam.y * (xs.y - gg.y - qq.y);
            g2.z = gg.z + lam.z * (xs.z - gg.z - qq.z);
            g2.w = gg.w + lam.w * (xs.w - gg.w - qq.w);
            *reinterpret_cast<float4*>(g_grad + idx) = g2;
        }
    }
}

// =====================================================================
// host launcher
// =====================================================================
extern "C" void kernel_launch(void* const* d_in, const int* in_sizes, int n_in,
                              void* d_out, int out_size)
{
    const float* y     = (const float*)d_in[0];
    const float* atoms = (const float*)d_in[1];
    float* out = (float*)d_out;

    float *p_anorm, *p_X, *p_q, *p_c, *p_invyn, *p_ynorm;
    cudaGetSymbolAddress((void**)&p_anorm, g_anorm);
    cudaGetSymbolAddress((void**)&p_X,     g_X);
    cudaGetSymbolAddress((void**)&p_q,     g_q);
    cudaGetSymbolAddress((void**)&p_c,     g_c);
    cudaGetSymbolAddress((void**)&p_invyn, g_invyn);
    cudaGetSymbolAddress((void**)&p_ynorm, g_ynorm);

    const int ESM = ENTCAP * 6;   // 49152 bytes
    cudaFuncSetAttribute(xsm_mma_kernel,
                         cudaFuncAttributeMaxDynamicSharedMemorySize, SMEM_DYN);
    cudaFuncSetAttribute(nds_pass_kernel,
                         cudaFuncAttributeMaxDynamicSharedMemorySize, ESM);
    cudaFuncSetAttribute(nds_lamden_kernel,
                         cudaFuncAttributeMaxDynamicSharedMemorySize, ESM);
    cudaFuncSetAttribute(nds_finalize_kernel,
                         cudaFuncAttributeMaxDynamicSharedMemorySize, ESM);

    ynorm_kernel<<<BD / 8, 256>>>(y);
    anorm_kernel<<<AD, 256>>>(atoms);

    gemm_kernel<false, false, 0><<<dim3(AD / 128, AD / 128), 256>>>(
        p_anorm, p_anorm, p_X, AD, AD, DD, DD, DD, AD, nullptr);
    rowsumX_kernel<<<AD / 8, 256>>>();
    xperm_kernel<<<1024, 256>>>();

    gemm_kernel<false, false, 1><<<dim3(BD / 128, AD / 128), 256>>>(
        p_anorm, y, p_q, AD, BD, DD, DD, DD, BD, p_invyn);

    colq_alpha_kernel<<<BD / 256, 256>>>();

    for (int t = 0; t < NONDIFF; t++) {
        nds_pass_kernel<<<NBLK, 256, ESM>>>(t);
        argmin_parts_kernel<<<AD / 8, 256>>>();
        nds_lamden_kernel<<<NBLK, 256, ESM>>>(t);
        nds_lamalpha_kernel<<<BD / 256, 256>>>();
        nds_entryupd_kernel<<<(t + 1) * 4, 256>>>(t);
    }
    nds_finalize_kernel<<<NBLK, 256, ESM>>>();

    for (int s = 0; s < DIFFST; s++) {
        softmaxT_kernel<<<NBLK, 256>>>();
        xsm_mma_kernel<<<dim3(BD / 128, AD / 128), 256, SMEM_DYN>>>();
        d_reduce_kernel<<<NBLK, 256>>>();
        if (s + 1 < DIFFST) d_update_kernel<false><<<NBLK, 256>>>();
        else                d_update_kernel<true ><<<NBLK, 256>>>();
    }

    gemm_kernel<true, true, 2><<<dim3(DD / 128, BD / 128), 256>>>(
        p_c, p_anorm, out, BD, DD, AD, BD, DD, DD, p_ynorm);
}

// round 11
// speedup vs baseline: 3.9664x; 3.9664x over previous
#include <cuda_runtime.h>
#include <math.h>
#include <stdint.h>

#define AD 1024
#define BD 16384
#define DD 768
#define TEMPC 100.0f
#define EPSC 1e-8f
#define NONDIFF 30
#define DIFFST 10
#define NBLK 256            /* BD / 64 column blocks */

// ---- device scratch (allocation-free: __device__ globals) ----
__device__ float g_anorm[AD * DD];
__device__ float g_X[AD * AD];
__device__ float g_Xp[AD * AD];              // fragment-order tf32 X (A operand)
__device__ float g_anAp[AD * DD];            // fragment-order tf32 anorm (A operand, q gemm)
__device__ float g_yp[(size_t)BD * DD];      // fragment-order tf32 y*invyn (B operand, q gemm)
__device__ float g_cTp[(size_t)BD * AD];     // fragment-order tf32 c^T (A operand, recon)
__device__ float g_anTp[DD * AD];            // fragment-order tf32 anorm^T (B operand, recon)
__device__ float g_rsx[AD];
__device__ float g_q[AD * BD];
__device__ float g_c[AD * BD];
__device__ float g_grad[AD * BD];
__device__ float g_sm[AD * BD];
__device__ float g_smTp[(size_t)BD * AD];    // fragment-order tf32 softmax (B operand)
__device__ float g_xsm[AD * BD];
__device__ float g_ynorm[BD];
__device__ float g_invyn[BD];
__device__ int   g_amin[AD];
__device__ float g_num[BD];
__device__ float g_denpart[NBLK];
__device__ unsigned long long g_minp[AD * NBLK];

__device__ __forceinline__ float tf32_rna(float x) {
    float r;
    asm("cvt.rna.tf32.f32 %0, %1;" : "=f"(r) : "f"(x));
    return r;
}
__device__ __forceinline__ uint32_t smem_u32(const void* p) {
    uint32_t a;
    asm("{ .reg .u64 t; cvta.to.shared.u64 t, %1; cvt.u32.u64 %0, t; }" : "=r"(a) : "l"(p));
    return a;
}
__device__ __forceinline__ unsigned fenc(float v) {
    unsigned b = __float_as_uint(v);
    return b ^ ((b & 0x80000000u) ? 0xFFFFFFFFu : 0x80000000u);
}
__device__ __forceinline__ unsigned long long packmin(float v, int j) {
    return ((unsigned long long)fenc(v) << 32) | (unsigned)j;
}
#define CP16(dst, src) asm volatile("cp.async.cg.shared.global [%0], [%1], 16;" :: "r"(dst), "l"(src))
#define CP_COMMIT()    asm volatile("cp.async.commit_group;" ::: "memory")
#define CP_WAIT(n)     asm volatile("cp.async.wait_group %0;" :: "n"(n) : "memory")

__device__ __forceinline__ void mma_tf32_16n8k8(float* c, const uint32_t* a, const uint32_t* b) {
    asm volatile(
        "mma.sync.aligned.m16n8k8.row.col.f32.tf32.tf32.f32 "
        "{%0,%1,%2,%3}, {%4,%5,%6,%7}, {%8,%9}, {%0,%1,%2,%3};"
        : "+f"(c[0]), "+f"(c[1]), "+f"(c[2]), "+f"(c[3])
        : "r"(a[0]), "r"(a[1]), "r"(a[2]), "r"(a[3]), "r"(b[0]), "r"(b[1]));
}

// =====================================================================
// init kernels
// =====================================================================
__global__ void ynorm_kernel(const float* __restrict__ y) {
    int w = (blockIdx.x * blockDim.x + threadIdx.x) >> 5;
    int lane = threadIdx.x & 31;
    if (w >= BD) return;
    const float* row = y + (size_t)w * DD;
    float s = 0.f;
    for (int d = lane; d < DD; d += 32) s += fabsf(row[d]);
#pragma unroll
    for (int o = 16; o; o >>= 1) s += __shfl_xor_sync(0xffffffffu, s, o);
    if (!lane) { g_ynorm[w] = s; g_invyn[w] = 1.0f / s; }
}

__global__ void anorm_kernel(const float* __restrict__ atoms) {
    int r = blockIdx.x;
    const float* row = atoms + (size_t)r * DD;
    __shared__ float red[256];
    float s = 0.f;
    for (int d = threadIdx.x; d < DD; d += 256) s += fabsf(row[d]);
    red[threadIdx.x] = s;
    __syncthreads();
    for (int o = 128; o; o >>= 1) {
        if (threadIdx.x < o) red[threadIdx.x] += red[threadIdx.x + o];
        __syncthreads();
    }
    float nrm = red[0];
    for (int d = threadIdx.x; d < DD; d += 256)
        g_anorm[r * DD + d] = row[d] / nrm;
}

__global__ void rowsumX_kernel() {
    int w = (blockIdx.x * blockDim.x + threadIdx.x) >> 5;
    int lane = threadIdx.x & 31;
    if (w >= AD) return;
    float s = 0.f;
    for (int k = lane; k < AD; k += 32) s += g_X[w * AD + k];
#pragma unroll
    for (int o = 16; o; o >>= 1) s += __shfl_xor_sync(0xffffffffu, s, o);
    if (!lane) g_rsx[w] = s;
}

// X -> A-fragment order: [mt][kt 128][lane][4]
__global__ void xperm_kernel() {
    int idx = blockIdx.x * 256 + threadIdx.x;
    int L = idx & 31, kt = (idx >> 5) & 127, mt = idx >> 12;
    int r = mt * 16 + (L >> 2), c = kt * 8 + (L & 3);
    float4 v;
    v.x = tf32_rna(g_X[r * AD + c]);
    v.y = tf32_rna(g_X[(r + 8) * AD + c]);
    v.z = tf32_rna(g_X[r * AD + c + 4]);
    v.w = tf32_rna(g_X[(r + 8) * AD + c + 4]);
    *reinterpret_cast<float4*>(g_Xp + (size_t)idx * 4) = v;
}

// anorm [AD x DD] -> A-fragment order (q gemm), kt_tot = 96
__global__ void anAperm_kernel() {
    int idx = blockIdx.x * 256 + threadIdx.x;      // 196608 threads
    int L = idx & 31, kt = (idx >> 5) % 96, mt = idx / (32 * 96);
    int r = mt * 16 + (L >> 2), c = kt * 8 + (L & 3);
    float4 v;
    v.x = tf32_rna(g_anorm[r * DD + c]);
    v.y = tf32_rna(g_anorm[(r + 8) * DD + c]);
    v.z = tf32_rna(g_anorm[r * DD + c + 4]);
    v.w = tf32_rna(g_anorm[(r + 8) * DD + c + 4]);
    *reinterpret_cast<float4*>(g_anAp + (size_t)idx * 4) = v;
}

// y*invyn [BD x DD] -> B-fragment order (q gemm), kt_tot = 96
__global__ void yBperm_kernel(const float* __restrict__ y) {
    int idx = blockIdx.x * 256 + threadIdx.x;      // 6291456 threads
    int L = idx & 31, kt = (idx >> 5) % 96, nt = idx / (32 * 96);
    int n = nt * 8 + (L >> 2), k = kt * 8 + (L & 3);
    float iv = g_invyn[n];
    float2 v;
    v.x = tf32_rna(y[(size_t)n * DD + k] * iv);
    v.y = tf32_rna(y[(size_t)n * DD + k + 4] * iv);
    *reinterpret_cast<float2*>(g_yp + (size_t)idx * 2) = v;
}

// c^T [BD x AD] -> A-fragment order (recon), kt_tot = 128
__global__ void cAperm_kernel() {
    int idx = blockIdx.x * 256 + threadIdx.x;      // 4194304 threads
    int L = idx & 31, kt = (idx >> 5) & 127, mt = idx >> 12;
    int r = mt * 16 + (L >> 2), ca = kt * 8 + (L & 3);
    float4 v;
    v.x = tf32_rna(g_c[(size_t)ca * BD + r]);
    v.y = tf32_rna(g_c[(size_t)ca * BD + r + 8]);
    v.z = tf32_rna(g_c[(size_t)(ca + 4) * BD + r]);
    v.w = tf32_rna(g_c[(size_t)(ca + 4) * BD + r + 8]);
    *reinterpret_cast<float4*>(g_cTp + (size_t)idx * 4) = v;
}

// anorm^T [DD x AD] -> B-fragment order (recon), kt_tot = 128
__global__ void anBperm_kernel() {
    int idx = blockIdx.x * 256 + threadIdx.x;      // 393216 threads
    int L = idx & 31, kt = (idx >> 5) & 127, nt = idx >> 12;
    int n = nt * 8 + (L >> 2), k = kt * 8 + (L & 3);
    float2 v;
    v.x = tf32_rna(g_anorm[(size_t)k * DD + n]);
    v.y = tf32_rna(g_anorm[(size_t)(k + 4) * DD + n]);
    *reinterpret_cast<float2*>(g_anTp + (size_t)idx * 2) = v;
}

__global__ void init_kernel() {
    size_t i4 = ((size_t)blockIdx.x * 256 + threadIdx.x) * 4;
    int a = (int)(i4 / BD);
    float rs = g_rsx[a] * (1.0f / AD);
    float4 q4 = *reinterpret_cast<const float4*>(g_q + i4);
    float4 g;
    g.x = rs - q4.x; g.y = rs - q4.y; g.z = rs - q4.z; g.w = rs - q4.w;
    *reinterpret_cast<float4*>(g_grad + i4) = g;
    float4 cc = make_float4(1.0f / AD, 1.0f / AD, 1.0f / AD, 1.0f / AD);
    *reinterpret_cast<float4*>(g_c + i4) = cc;
}

// =====================================================================
// fp32 SIMT GEMM (X only — full precision)
// =====================================================================
template <bool AKM, bool BKM, int SCALE>
__global__ void __launch_bounds__(256) gemm_kernel(
    const float* __restrict__ A, const float* __restrict__ B, float* __restrict__ C,
    int M, int N, int K, int lda, int ldb, int ldc, const float* __restrict__ scale)
{
    __shared__ float As[16][132];
    __shared__ float Bs[16][132];
    const int tid = threadIdx.x;
    const int tx = tid & 15, ty = tid >> 4;
    const int m0 = blockIdx.y * 128, n0 = blockIdx.x * 128;
    float acc[8][8];
#pragma unroll
    for (int i = 0; i < 8; i++)
#pragma unroll
        for (int j = 0; j < 8; j++) acc[i][j] = 0.f;

    for (int k0 = 0; k0 < K; k0 += 16) {
#pragma unroll
        for (int i = 0; i < 2; i++) {
            int lin = tid + i * 256;
            if (AKM) {
                int kk = lin >> 5, mm = (lin & 31) << 2;
                float4 v = *reinterpret_cast<const float4*>(A + (size_t)(k0 + kk) * lda + (m0 + mm));
                *reinterpret_cast<float4*>(&As[kk][mm]) = v;
            } else {
                int mm = lin >> 2, kk = (lin & 3) << 2;
                float4 v = *reinterpret_cast<const float4*>(A + (size_t)(m0 + mm) * lda + (k0 + kk));
                As[kk + 0][mm] = v.x; As[kk + 1][mm] = v.y;
                As[kk + 2][mm] = v.z; As[kk + 3][mm] = v.w;
            }
        }
#pragma unroll
        for (int i = 0; i < 2; i++) {
            int lin = tid + i * 256;
            if (BKM) {
                int kk = lin >> 5, nn = (lin & 31) << 2;
                float4 v = *reinterpret_cast<const float4*>(B + (size_t)(k0 + kk) * ldb + (n0 + nn));
                *reinterpret_cast<float4*>(&Bs[kk][nn]) = v;
            } else {
                int nn = lin >> 2, kk = (lin & 3) << 2;
                float4 v = *reinterpret_cast<const float4*>(B + (size_t)(n0 + nn) * ldb + (k0 + kk));
                Bs[kk + 0][nn] = v.x; Bs[kk + 1][nn] = v.y;
                Bs[kk + 2][nn] = v.z; Bs[kk + 3][nn] = v.w;
            }
        }
        __syncthreads();
#pragma unroll
        for (int k = 0; k < 16; k++) {
            float af[8], bf[8];
            *reinterpret_cast<float4*>(&af[0]) = *reinterpret_cast<float4*>(&As[k][ty * 8]);
            *reinterpret_cast<float4*>(&af[4]) = *reinterpret_cast<float4*>(&As[k][ty * 8 + 4]);
            *reinterpret_cast<float4*>(&bf[0]) = *reinterpret_cast<float4*>(&Bs[k][tx * 8]);
            *reinterpret_cast<float4*>(&bf[4]) = *reinterpret_cast<float4*>(&Bs[k][tx * 8 + 4]);
#pragma unroll
            for (int i = 0; i < 8; i++)
#pragma unroll
                for (int j = 0; j < 8; j++) acc[i][j] += af[i] * bf[j];
        }
        __syncthreads();
    }
#pragma unroll
    for (int i = 0; i < 8; i++) {
        int m = m0 + ty * 8 + i;
        float rowf = (SCALE == 2) ? scale[m] : 1.f;
#pragma unroll
        for (int j = 0; j < 8; j++) {
            float f = (SCALE == 1) ? scale[n0 + tx * 8 + j] : rowf;
            C[(size_t)m * ldc + n0 + tx * 8 + j] = acc[i][j] * f;
        }
    }
}

// =====================================================================
// generic tf32 mma GEMM on fragment-order operands.
// A frag: [mt][kt_tot][32][4]; B frag: [nt][kt_tot][32][2].
// CTA 128m x 128n, K chunks of 32 (4 k_tiles), double-buffered cp.async.
// SCALE: 0 none, 2: C *= scale[m].
// =====================================================================
#define A_CH 16384
#define B_CH 16384
#define SMEM_DYN (2 * (A_CH + B_CH))

template <int SCALE>
__global__ void __launch_bounds__(256, 2) mma_gemm_kernel(
    const float* __restrict__ Af, const float* __restrict__ Bf,
    float* __restrict__ C, int kt_tot, int nck, int ldc,
    const float* __restrict__ scale)
{
    extern __shared__ char smc[];
    const uint32_t sb = smem_u32(smc);
    const int tid = threadIdx.x;
    const int wid = tid >> 5, lane = tid & 31;
    const int m0 = blockIdx.y * 128, n0 = blockIdx.x * 128;
    const int mt0 = m0 >> 4;
    const int nt0 = n0 >> 3;

    float acc[2][8][4];
#pragma unroll
    for (int i = 0; i < 2; i++)
#pragma unroll
        for (int j = 0; j < 8; j++)
#pragma unroll
            for (int v = 0; v < 4; v++) acc[i][j][v] = 0.f;

#define PREFETCH(CK, BUF) do { \
    const int _kt0 = (CK) * 4; \
    _Pragma("unroll") \
    for (int s = 0; s < 4; s++) { \
        int idx = tid + s * 256; \
        int mtl = idx >> 7, remA = idx & 127; \
        const float* srcA = Af + ((size_t)(mt0 + mtl) * kt_tot + _kt0) * 128 + remA * 4; \
        CP16(sb + (BUF) * (A_CH + B_CH) + (mtl * 128 + remA) * 16, srcA); \
        int ntl = idx >> 6, remB = idx & 63; \
        const float* srcB = Bf + ((size_t)(nt0 + ntl) * kt_tot + _kt0) * 64 + remB * 4; \
        CP16(sb + (BUF) * (A_CH + B_CH) + A_CH + (ntl * 64 + remB) * 16, srcB); \
    } \
    CP_COMMIT(); } while (0)

    PREFETCH(0, 0);

    const int wm = (wid >> 1) * 2;
    const int wn = (wid & 1) * 8;

    for (int ck = 0; ck < nck; ck++) {
        const int buf = ck & 1;
        if (ck + 1 < nck) {
            PREFETCH(ck + 1, (ck + 1) & 1);
            CP_WAIT(1);
        } else {
            CP_WAIT(0);
        }
        __syncthreads();

        const char* Abase = smc + buf * (A_CH + B_CH);
        const char* Bbase = Abase + A_CH;

#pragma unroll
        for (int ktl = 0; ktl < 4; ktl++) {
            uint32_t afr[2][4];
#pragma unroll
            for (int i = 0; i < 2; i++) {
                uint4 v = *reinterpret_cast<const uint4*>(
                    Abase + (((wm + i) * 4 + ktl) * 32 + lane) * 16);
                afr[i][0] = v.x; afr[i][1] = v.y; afr[i][2] = v.z; afr[i][3] = v.w;
            }
            uint32_t bfr[8][2];
#pragma unroll
            for (int j = 0; j < 8; j++) {
                uint2 v = *reinterpret_cast<const uint2*>(
                    Bbase + (((wn + j) * 4 + ktl) * 32 + lane) * 8);
                bfr[j][0] = v.x; bfr[j][1] = v.y;
            }
#pragma unroll
            for (int i = 0; i < 2; i++)
#pragma unroll
                for (int j = 0; j < 8; j++)
                    mma_tf32_16n8k8(acc[i][j], afr[i], bfr[j]);
        }
        __syncthreads();
    }
#undef PREFETCH

    const int grp = lane >> 2, q4 = lane & 3;
#pragma unroll
    for (int i = 0; i < 2; i++) {
        int row = m0 + (wid >> 1) * 32 + i * 16 + grp;
        float s0 = (SCALE == 2) ? scale[row] : 1.f;
        float s1 = (SCALE == 2) ? scale[row + 8] : 1.f;
#pragma unroll
        for (int j = 0; j < 8; j++) {
            int col = n0 + (wid & 1) * 64 + j * 8 + q4 * 2;
            *reinterpret_cast<float2*>(C + (size_t)row * ldc + col) =
                make_float2(acc[i][j][0] * s0, acc[i][j][1] * s0);
            *reinterpret_cast<float2*>(C + (size_t)(row + 8) * ldc + col) =
                make_float2(acc[i][j][2] * s1, acc[i][j][3] * s1);
        }
    }
}

// =====================================================================
// full argmin (step 0 only)
// =====================================================================
__global__ void __launch_bounds__(256) argmin_full_kernel() {
    const int a = blockIdx.x;
    const float* row = g_grad + (size_t)a * BD;
    unsigned long long best = ~0ull;
    for (int it = 0; it < 16; it++) {
        int j = threadIdx.x * 4 + it * 1024;
        float4 v = *reinterpret_cast<const float4*>(row + j);
        unsigned long long k0 = packmin(v.x, j);
        unsigned long long k1 = packmin(v.y, j + 1);
        unsigned long long k2 = packmin(v.z, j + 2);
        unsigned long long k3 = packmin(v.w, j + 3);
        if (k1 < k0) k0 = k1;
        if (k3 < k2) k2 = k3;
        if (k2 < k0) k0 = k2;
        if (k0 < best) best = k0;
    }
    __shared__ unsigned long long sk[256];
    sk[threadIdx.x] = best;
    __syncthreads();
    for (int o = 128; o; o >>= 1) {
        if (threadIdx.x < o && sk[threadIdx.x + o] < sk[threadIdx.x])
            sk[threadIdx.x] = sk[threadIdx.x + o];
        __syncthreads();
    }
    if (!threadIdx.x) g_amin[a] = (int)(sk[0] & 0xFFFFFFFFu);
}

__global__ void __launch_bounds__(256) argmin_parts_kernel() {
    const int wid = threadIdx.x >> 5, lane = threadIdx.x & 31;
    const int a = blockIdx.x * 8 + wid;
    unsigned long long best = ~0ull;
#pragma unroll
    for (int k = 0; k < NBLK / 32; k++) {
        unsigned long long v = g_minp[(size_t)a * NBLK + lane + k * 32];
        if (v < best) best = v;
    }
#pragma unroll
    for (int o = 16; o; o >>= 1) {
        unsigned long long v = __shfl_down_sync(0xffffffffu, best, o);
        if (v < best) best = v;
    }
    if (!lane) g_amin[a] = (int)(best & 0xFFFFFFFFu);
}

// =====================================================================
// selection list
// =====================================================================
__device__ __forceinline__ void build_sel_list(
    const int* amin_s, int j0, int* sel_a, int* sel_j, int* nsel_s,
    int tid)
{
    if (tid < 32) {
        int cnt = 0;
        for (int base = 0; base < AD; base += 32) {
            int a = base + tid;
            int jm = amin_s[a];
            bool mt = (jm >= j0 && jm < j0 + 64);
            unsigned mask = __ballot_sync(0xffffffffu, mt);
            if (mt) {
                int p = cnt + __popc(mask & ((1u << tid) - 1u));
                sel_a[p] = a; sel_j[p] = jm;
            }
            cnt += __popc(mask);
        }
        if (tid == 0) *nsel_s = cnt;
    }
}

// =====================================================================
// nondiff step kernels (R9 versions)
// =====================================================================
__global__ void __launch_bounds__(256) nd_reduce_kernel() {
    const int tid = threadIdx.x, tx = tid & 15, ty = tid >> 4;
    const int j0 = blockIdx.x * 64, jb = j0 + tx * 4;
    __shared__ int amin_s[AD];
    __shared__ int sel_a[AD], sel_j[AD], nsel_s;
    for (int a = tid; a < AD; a += 256) amin_s[a] = g_amin[a];
    __syncthreads();
    build_sel_list(amin_s, j0, sel_a, sel_j, &nsel_s, tid);
    __syncthreads();
    const int ns = nsel_s;

    float4 num4 = {0, 0, 0, 0}, den4 = {0, 0, 0, 0};
    for (int a = ty; a < AD; a += 16) {
        size_t idx = (size_t)a * BD + jb;
        float4 cc = *reinterpret_cast<const float4*>(g_c + idx);
        float4 gg = *reinterpret_cast<const float4*>(g_grad + idx);
        float4 qq = *reinterpret_cast<const float4*>(g_q + idx);
        float4 S = {0, 0, 0, 0};
        for (int e = 0; e < ns; e++) {
            float xv = g_X[a * AD + sel_a[e]];
            int d = sel_j[e] - jb;
            S.x += (d == 0) ? xv : 0.f;
            S.y += (d == 1) ? xv : 0.f;
            S.z += (d == 2) ? xv : 0.f;
            S.w += (d == 3) ? xv : 0.f;
        }
        int am = amin_s[a];
        float4 dd, xd;
        dd.x = ((am == jb + 0) ? 1.f : 0.f) - cc.x;
        dd.y = ((am == jb + 1) ? 1.f : 0.f) - cc.y;
        dd.z = ((am == jb + 2) ? 1.f : 0.f) - cc.z;
        dd.w = ((am == jb + 3) ? 1.f : 0.f) - cc.w;
        xd.x = S.x - gg.x - qq.x; xd.y = S.y - gg.y - qq.y;
        xd.z = S.z - gg.z - qq.z; xd.w = S.w - gg.w - qq.w;
        num4.x += dd.x * gg.x; num4.y += dd.y * gg.y;
        num4.z += dd.z * gg.z; num4.w += dd.w * gg.w;
        den4.x += dd.x * xd.x; den4.y += dd.y * xd.y;
        den4.z += dd.z * xd.z; den4.w += dd.w * xd.w;
    }
    __shared__ float4 rn[16][17], rd[16][17];
    __shared__ float colden[16];
    rn[ty][tx] = num4; rd[ty][tx] = den4;
    __syncthreads();
    if (ty == 0) {
        float4 n = rn[0][tx], d = rd[0][tx];
        for (int t = 1; t < 16; t++) {
            float4 n2 = rn[t][tx], d2 = rd[t][tx];
            n.x += n2.x; n.y += n2.y; n.z += n2.z; n.w += n2.w;
            d.x += d2.x; d.y += d2.y; d.z += d2.z; d.w += d2.w;
        }
        *reinterpret_cast<float4*>(g_num + jb) = n;
        colden[tx] = d.x + d.y + d.z + d.w;
    }
    __syncthreads();
    if (tid == 0) {
        float s = 0.f;
        for (int t = 0; t < 16; t++) s += colden[t];
        g_denpart[blockIdx.x] = s;
    }
}

__global__ void __launch_bounds__(256) nd_update_kernel() {
    const int tid = threadIdx.x, tx = tid & 15, ty = tid >> 4;
    const int j0 = blockIdx.x * 64, jb = j0 + tx * 4;
    __shared__ float red[256];
    __shared__ int amin_s[AD];
    __shared__ int sel_a[AD], sel_j[AD], nsel_s;
    red[tid] = g_denpart[tid];
    for (int a = tid; a < AD; a += 256) amin_s[a] = g_amin[a];
    __syncthreads();
    for (int o = 128; o; o >>= 1) {
        if (tid < o) red[tid] += red[tid + o];
        __syncthreads();
    }
    build_sel_list(amin_s, j0, sel_a, sel_j, &nsel_s, tid);
    __syncthreads();
    const int ns = nsel_s;
    const float denom = red[0] + EPSC;
    float4 nm = *reinterpret_cast<const float4*>(g_num + jb);
    float4 lam;
    lam.x = fminf(fmaxf(-nm.x / denom, 0.f), 1.f);
    lam.y = fminf(fmaxf(-nm.y / denom, 0.f), 1.f);
    lam.z = fminf(fmaxf(-nm.z / denom, 0.f), 1.f);
    lam.w = fminf(fmaxf(-nm.w / denom, 0.f), 1.f);

    for (int a = ty; a < AD; a += 16) {
        size_t idx = (size_t)a * BD + jb;
        float4 cc = *reinterpret_cast<const float4*>(g_c + idx);
        float4 gg = *reinterpret_cast<const float4*>(g_grad + idx);
        float4 qq = *reinterpret_cast<const float4*>(g_q + idx);
        float4 S = {0, 0, 0, 0};
        for (int e = 0; e < ns; e++) {
            float xv = g_X[a * AD + sel_a[e]];
            int d = sel_j[e] - jb;
            S.x += (d == 0) ? xv : 0.f;
            S.y += (d == 1) ? xv : 0.f;
            S.z += (d == 2) ? xv : 0.f;
            S.w += (d == 3) ? xv : 0.f;
        }
        int am = amin_s[a];
        float4 dd, xd, c2, g2;
        dd.x = ((am == jb + 0) ? 1.f : 0.f) - cc.x;
        dd.y = ((am == jb + 1) ? 1.f : 0.f) - cc.y;
        dd.z = ((am == jb + 2) ? 1.f : 0.f) - cc.z;
        dd.w = ((am == jb + 3) ? 1.f : 0.f) - cc.w;
        xd.x = S.x - gg.x - qq.x; xd.y = S.y - gg.y - qq.y;
        xd.z = S.z - gg.z - qq.z; xd.w = S.w - gg.w - qq.w;
        c2.x = cc.x + lam.x * dd.x; c2.y = cc.y + lam.y * dd.y;
        c2.z = cc.z + lam.z * dd.z; c2.w = cc.w + lam.w * dd.w;
        g2.x = gg.x + lam.x * xd.x; g2.y = gg.y + lam.y * xd.y;
        g2.z = gg.z + lam.z * xd.z; g2.w = gg.w + lam.w * xd.w;
        *reinterpret_cast<float4*>(g_c + idx)    = c2;
        *reinterpret_cast<float4*>(g_grad + idx) = g2;

        unsigned long long best = packmin(g2.x, jb);
        unsigned long long k1 = packmin(g2.y, jb + 1);
        unsigned long long k2 = packmin(g2.z, jb + 2);
        unsigned long long k3 = packmin(g2.w, jb + 3);
        if (k1 < best) best = k1;
        if (k2 < best) best = k2;
        if (k3 < best) best = k3;
#pragma unroll
        for (int o = 8; o; o >>= 1) {
            unsigned long long v = __shfl_down_sync(0xffffffffu, best, o, 16);
            if (v < best) best = v;
        }
        if (tx == 0) g_minp[(size_t)a * NBLK + blockIdx.x] = best;
    }
}

// =====================================================================
// softmax (vectorized) + fragment-order tf32 B operand writer
// =====================================================================
__global__ void __launch_bounds__(256) softmaxT_kernel() {
    const int tid = threadIdx.x, tx = tid & 15, ty = tid >> 4;
    const int j0 = blockIdx.x * 64, jb = j0 + tx * 4;

    float4 m4 = {-INFINITY, -INFINITY, -INFINITY, -INFINITY};
    float4 s4 = {0, 0, 0, 0};
    for (int a = ty; a < AD; a += 16) {
        float4 g = *reinterpret_cast<const float4*>(g_grad + (size_t)a * BD + jb);
        float v;
        v = -TEMPC * g.x; if (v > m4.x) { s4.x = s4.x * expf(m4.x - v) + 1.f; m4.x = v; } else s4.x += expf(v - m4.x);
        v = -TEMPC * g.y; if (v > m4.y) { s4.y = s4.y * expf(m4.y - v) + 1.f; m4.y = v; } else s4.y += expf(v - m4.y);
        v = -TEMPC * g.z; if (v > m4.z) { s4.z = s4.z * expf(m4.z - v) + 1.f; m4.z = v; } else s4.z += expf(v - m4.z);
        v = -TEMPC * g.w; if (v > m4.w) { s4.w = s4.w * expf(m4.w - v) + 1.f; m4.w = v; } else s4.w += expf(v - m4.w);
    }
    __shared__ float4 mm[16][17], ss[16][17];
    __shared__ float4 fm[16], fsinv[16];
    mm[ty][tx] = m4; ss[ty][tx] = s4;
    __syncthreads();
    if (ty == 0) {
        float4 M = mm[0][tx], S = ss[0][tx];
        for (int t = 1; t < 16; t++) {
            float4 m2 = mm[t][tx], s2 = ss[t][tx];
            float Mn;
            Mn = fmaxf(M.x, m2.x); S.x = S.x * expf(M.x - Mn) + s2.x * expf(m2.x - Mn); M.x = Mn;
            Mn = fmaxf(M.y, m2.y); S.y = S.y * expf(M.y - Mn) + s2.y * expf(m2.y - Mn); M.y = Mn;
            Mn = fmaxf(M.z, m2.z); S.z = S.z * expf(M.z - Mn) + s2.z * expf(m2.z - Mn); M.z = Mn;
            Mn = fmaxf(M.w, m2.w); S.w = S.w * expf(M.w - Mn) + s2.w * expf(m2.w - Mn); M.w = Mn;
        }
        fm[tx] = M;
        fsinv[tx] = make_float4(1.f / S.x, 1.f / S.y, 1.f / S.z, 1.f / S.w);
    }
    __syncthreads();
    const float4 M4 = fm[tx];
    const float4 I4 = fsinv[tx];

    __shared__ float tile[32][68];
    const int L = tid & 31, nt = tid >> 5;
    for (int at = 0; at < 32; at++) {
        const int a0 = at * 32;
#pragma unroll
        for (int half = 0; half < 2; half++) {
            int aa = ty + half * 16;
            size_t idx = (size_t)(a0 + aa) * BD + jb;
            float4 g = *reinterpret_cast<const float4*>(g_grad + idx);
            float4 e;
            e.x = expf(-TEMPC * g.x - M4.x) * I4.x;
            e.y = expf(-TEMPC * g.y - M4.y) * I4.y;
            e.z = expf(-TEMPC * g.z - M4.z) * I4.z;
            e.w = expf(-TEMPC * g.w - M4.w) * I4.w;
            *reinterpret_cast<float4*>(g_sm + idx) = e;
            tile[aa][tx * 4 + 0] = e.x;
            tile[aa][tx * 4 + 1] = e.y;
            tile[aa][tx * 4 + 2] = e.z;
            tile[aa][tx * 4 + 3] = e.w;
        }
        __syncthreads();
#pragma unroll
        for (int kt = 0; kt < 4; kt++) {
            float v0 = tile[kt * 8 + (L & 3)][nt * 8 + (L >> 2)];
            float v1 = tile[kt * 8 + (L & 3) + 4][nt * 8 + (L >> 2)];
            size_t o = (((size_t)(j0 / 8 + nt) * 128 + (at * 4 + kt)) * 32 + L) * 2;
            *reinterpret_cast<float2*>(g_smTp + o) =
                make_float2(tf32_rna(v0), tf32_rna(v1));
        }
        __syncthreads();
    }
}

// =====================================================================
// diff step reduce / update (R9 versions)
// =====================================================================
__global__ void __launch_bounds__(256) d_reduce_kernel() {
    const int tid = threadIdx.x, tx = tid & 15, ty = tid >> 4;
    const int jb = blockIdx.x * 64 + tx * 4;
    float4 num4 = {0, 0, 0, 0}, den4 = {0, 0, 0, 0};
    for (int a = ty; a < AD; a += 16) {
        size_t idx = (size_t)a * BD + jb;
        float4 sm = *reinterpret_cast<const float4*>(g_sm + idx);
        float4 cc = *reinterpret_cast<const float4*>(g_c + idx);
        float4 xs = *reinterpret_cast<const float4*>(g_xsm + idx);
        float4 gg = *reinterpret_cast<const float4*>(g_grad + idx);
        float4 qq = *reinterpret_cast<const float4*>(g_q + idx);
        float4 dd, xd;
        dd.x = sm.x - cc.x; dd.y = sm.y - cc.y; dd.z = sm.z - cc.z; dd.w = sm.w - cc.w;
        xd.x = xs.x - gg.x - qq.x; xd.y = xs.y - gg.y - qq.y;
        xd.z = xs.z - gg.z - qq.z; xd.w = xs.w - gg.w - qq.w;
        num4.x += dd.x * gg.x; num4.y += dd.y * gg.y;
        num4.z += dd.z * gg.z; num4.w += dd.w * gg.w;
        den4.x += dd.x * xd.x; den4.y += dd.y * xd.y;
        den4.z += dd.z * xd.z; den4.w += dd.w * xd.w;
    }
    __shared__ float4 rn[16][17], rd[16][17];
    __shared__ float colden[16];
    rn[ty][tx] = num4; rd[ty][tx] = den4;
    __syncthreads();
    if (ty == 0) {
        float4 n = rn[0][tx], d = rd[0][tx];
        for (int t = 1; t < 16; t++) {
            float4 n2 = rn[t][tx], d2 = rd[t][tx];
            n.x += n2.x; n.y += n2.y; n.z += n2.z; n.w += n2.w;
            d.x += d2.x; d.y += d2.y; d.z += d2.z; d.w += d2.w;
        }
        *reinterpret_cast<float4*>(g_num + jb) = n;
        colden[tx] = d.x + d.y + d.z + d.w;
    }
    __syncthreads();
    if (tid == 0) {
        float s = 0.f;
        for (int t = 0; t < 16; t++) s += colden[t];
        g_denpart[blockIdx.x] = s;
    }
}

template <bool LAST>
__global__ void __launch_bounds__(256) d_update_kernel() {
    const int tid = threadIdx.x, tx = tid & 15, ty = tid >> 4;
    const int jb = blockIdx.x * 64 + tx * 4;
    __shared__ float red[256];
    red[tid] = g_denpart[tid];
    __syncthreads();
    for (int o = 128; o; o >>= 1) {
        if (tid < o) red[tid] += red[tid + o];
        __syncthreads();
    }
    const float denom = red[0] + EPSC;
    float4 nm = *reinterpret_cast<const float4*>(g_num + jb);
    float4 lam;
    lam.x = fminf(fmaxf(-nm.x / denom, 0.f), 1.f);
    lam.y = fminf(fmaxf(-nm.y / denom, 0.f), 1.f);
    lam.z = fminf(fmaxf(-nm.z / denom, 0.f), 1.f);
    lam.w = fminf(fmaxf(-nm.w / denom, 0.f), 1.f);
    for (int a = ty; a < AD; a += 16) {
        size_t idx = (size_t)a * BD + jb;
        float4 sm = *reinterpret_cast<const float4*>(g_sm + idx);
        float4 cc = *reinterpret_cast<const float4*>(g_c + idx);
        float4 c2;
        c2.x = cc.x + lam.x * (sm.x - cc.x);
        c2.y = cc.y + lam.y * (sm.y - cc.y);
        c2.z = cc.z + lam.z * (sm.z - cc.z);
        c2.w = cc.w + lam.w * (sm.w - cc.w);
        *reinterpret_cast<float4*>(g_c + idx) = c2;
        if (!LAST) {
            float4 xs = *reinterpret_cast<const float4*>(g_xsm + idx);
            float4 gg = *reinterpret_cast<const float4*>(g_grad + idx);
            float4 qq = *reinterpret_cast<const float4*>(g_q + idx);
            float4 g2;
            g2.x = gg.x + lam.x * (xs.x - gg.x - qq.x);
            g2.y = gg.y + lam.y * (xs.y - gg.y - qq.y);
            g2.z = gg.z + lam.z * (xs.z - gg.z - qq.z);
            g2.w = gg.w + lam.w * (xs.w - gg.w - qq.w);
            *reinterpret_cast<float4*>(g_grad + idx) = g2;
        }
    }
}

// =====================================================================
// host launcher
// =====================================================================
extern "C" void kernel_launch(void* const* d_in, const int* in_sizes, int n_in,
                              void* d_out, int out_size)
{
    const float* y     = (const float*)d_in[0];
    const float* atoms = (const float*)d_in[1];
    float* out = (float*)d_out;

    float *p_anorm, *p_X, *p_Xp, *p_anAp, *p_yp, *p_cTp, *p_anTp, *p_q, *p_xsm, *p_smTp, *p_ynorm;
    cudaGetSymbolAddress((void**)&p_anorm, g_anorm);
    cudaGetSymbolAddress((void**)&p_X,     g_X);
    cudaGetSymbolAddress((void**)&p_Xp,    g_Xp);
    cudaGetSymbolAddress((void**)&p_anAp,  g_anAp);
    cudaGetSymbolAddress((void**)&p_yp,    g_yp);
    cudaGetSymbolAddress((void**)&p_cTp,   g_cTp);
    cudaGetSymbolAddress((void**)&p_anTp,  g_anTp);
    cudaGetSymbolAddress((void**)&p_q,     g_q);
    cudaGetSymbolAddress((void**)&p_xsm,   g_xsm);
    cudaGetSymbolAddress((void**)&p_smTp,  g_smTp);
    cudaGetSymbolAddress((void**)&p_ynorm, g_ynorm);

    cudaFuncSetAttribute(mma_gemm_kernel<0>,
                         cudaFuncAttributeMaxDynamicSharedMemorySize, SMEM_DYN);
    cudaFuncSetAttribute(mma_gemm_kernel<2>,
                         cudaFuncAttributeMaxDynamicSharedMemorySize, SMEM_DYN);

    ynorm_kernel<<<BD / 8, 256>>>(y);
    anorm_kernel<<<AD, 256>>>(atoms);

    // X = anorm @ anorm^T (SIMT fp32 — full precision for the step loop)
    gemm_kernel<false, false, 0><<<dim3(AD / 128, AD / 128), 256>>>(
        p_anorm, p_anorm, p_X, AD, AD, DD, DD, DD, AD, nullptr);
    rowsumX_kernel<<<AD / 8, 256>>>();
    xperm_kernel<<<1024, 256>>>();

    // q = anorm @ (y/|y|)^T via tf32 mma (invyn folded into B permute)
    anAperm_kernel<<<768, 256>>>();
    yBperm_kernel<<<24576, 256>>>(y);
    mma_gemm_kernel<0><<<dim3(BD / 128, AD / 128), 256, SMEM_DYN>>>(
        p_anAp, p_yp, p_q, 96, 24, BD, nullptr);

    init_kernel<<<(AD * BD) / 1024, 256>>>();

    argmin_full_kernel<<<AD, 256>>>();
    for (int s = 0; s < NONDIFF; s++) {
        nd_reduce_kernel<<<NBLK, 256>>>();
        nd_update_kernel<<<NBLK, 256>>>();
        if (s + 1 < NONDIFF) argmin_parts_kernel<<<AD / 8, 256>>>();
    }

    for (int s = 0; s < DIFFST; s++) {
        softmaxT_kernel<<<NBLK, 256>>>();
        mma_gemm_kernel<0><<<dim3(BD / 128, AD / 128), 256, SMEM_DYN>>>(
            p_Xp, p_smTp, p_xsm, 128, 32, BD, nullptr);
        d_reduce_kernel<<<NBLK, 256>>>();
        if (s + 1 < DIFFST) d_update_kernel<false><<<NBLK, 256>>>();
        else                d_update_kernel<true ><<<NBLK, 256>>>();
    }

    // recon = (c^T @ anorm) * |y| via tf32 mma
    cAperm_kernel<<<16384, 256>>>();
    anBperm_kernel<<<1536, 256>>>();
    mma_gemm_kernel<2><<<dim3(DD / 128, BD / 128), 256, SMEM_DYN>>>(
        p_cTp, p_anTp, out, 128, 32, DD, p_ynorm);
}

// round 14
// speedup vs baseline: 4.6790x; 1.1796x over previous
#include <cuda_runtime.h>
#include <math.h>
#include <stdint.h>

#define AD 1024
#define BD 16384
#define DD 768
#define TEMPC 100.0f
#define EPSC 1e-8f
#define NONDIFF 30
#define DIFFST 10
#define NBLK 256            /* BD / 64 column blocks */

// ---- device scratch (allocation-free: __device__ globals) ----
__device__ float g_anorm[AD * DD];
__device__ float g_X[AD * AD];
__device__ float g_Xp[AD * AD];
__device__ float g_anAp[AD * DD];
__device__ float g_yp[(size_t)BD * DD];
__device__ float g_cTp[(size_t)BD * AD];
__device__ float g_anTp[DD * AD];
__device__ float g_rsx[AD];
__device__ float g_q[AD * BD];
__device__ float g_c[AD * BD];
__device__ float g_grad[AD * BD];
__device__ float g_sm[AD * BD];
__device__ float g_smTp[(size_t)BD * AD];
__device__ float g_xsm[AD * BD];
__device__ float g_ynorm[BD];
__device__ float g_invyn[BD];
__device__ int   g_amin[AD];
__device__ float g_num[BD];
__device__ float g_den[BD];
__device__ float g_denpart[NBLK];
__device__ float g_lam[BD];
__device__ float g_colcg[BD];
__device__ float g_colcq[BD];
__device__ float g_gp[AD];
__device__ float g_qp[AD];
__device__ float g_pp[AD];
__device__ unsigned long long g_minp[AD * NBLK];

__device__ __forceinline__ float tf32_rna(float x) {
    float r;
    asm("cvt.rna.tf32.f32 %0, %1;" : "=f"(r) : "f"(x));
    return r;
}
__device__ __forceinline__ uint32_t smem_u32(const void* p) {
    uint32_t a;
    asm("{ .reg .u64 t; cvta.to.shared.u64 t, %1; cvt.u32.u64 %0, t; }" : "=r"(a) : "l"(p));
    return a;
}
__device__ __forceinline__ unsigned fenc(float v) {
    unsigned b = __float_as_uint(v);
    return b ^ ((b & 0x80000000u) ? 0xFFFFFFFFu : 0x80000000u);
}
__device__ __forceinline__ unsigned long long packmin(float v, int j) {
    return ((unsigned long long)fenc(v) << 32) | (unsigned)j;
}
#define CP16(dst, src) asm volatile("cp.async.cg.shared.global [%0], [%1], 16;" :: "r"(dst), "l"(src))
#define CP_COMMIT()    asm volatile("cp.async.commit_group;" ::: "memory")
#define CP_WAIT(n)     asm volatile("cp.async.wait_group %0;" :: "n"(n) : "memory")

__device__ __forceinline__ void mma_tf32_16n8k8(float* c, const uint32_t* a, const uint32_t* b) {
    asm volatile(
        "mma.sync.aligned.m16n8k8.row.col.f32.tf32.tf32.f32 "
        "{%0,%1,%2,%3}, {%4,%5,%6,%7}, {%8,%9}, {%0,%1,%2,%3};"
        : "+f"(c[0]), "+f"(c[1]), "+f"(c[2]), "+f"(c[3])
        : "r"(a[0]), "r"(a[1]), "r"(a[2]), "r"(a[3]), "r"(b[0]), "r"(b[1]));
}

// =====================================================================
// init kernels
// =====================================================================
__global__ void ynorm_kernel(const float* __restrict__ y) {
    int w = (blockIdx.x * blockDim.x + threadIdx.x) >> 5;
    int lane = threadIdx.x & 31;
    if (w >= BD) return;
    const float* row = y + (size_t)w * DD;
    float s = 0.f;
    for (int d = lane; d < DD; d += 32) s += fabsf(row[d]);
#pragma unroll
    for (int o = 16; o; o >>= 1) s += __shfl_xor_sync(0xffffffffu, s, o);
    if (!lane) { g_ynorm[w] = s; g_invyn[w] = 1.0f / s; }
}

__global__ void anorm_kernel(const float* __restrict__ atoms) {
    int r = blockIdx.x;
    const float* row = atoms + (size_t)r * DD;
    __shared__ float red[256];
    float s = 0.f;
    for (int d = threadIdx.x; d < DD; d += 256) s += fabsf(row[d]);
    red[threadIdx.x] = s;
    __syncthreads();
    for (int o = 128; o; o >>= 1) {
        if (threadIdx.x < o) red[threadIdx.x] += red[threadIdx.x + o];
        __syncthreads();
    }
    float nrm = red[0];
    for (int d = threadIdx.x; d < DD; d += 256)
        g_anorm[r * DD + d] = row[d] / nrm;
}

__global__ void rowsumX_kernel() {
    int w = (blockIdx.x * blockDim.x + threadIdx.x) >> 5;
    int lane = threadIdx.x & 31;
    if (w >= AD) return;
    float s = 0.f;
    for (int k = lane; k < AD; k += 32) s += g_X[w * AD + k];
#pragma unroll
    for (int o = 16; o; o >>= 1) s += __shfl_xor_sync(0xffffffffu, s, o);
    if (!lane) g_rsx[w] = s;
}

__global__ void xperm_kernel() {
    int idx = blockIdx.x * 256 + threadIdx.x;
    int L = idx & 31, kt = (idx >> 5) & 127, mt = idx >> 12;
    int r = mt * 16 + (L >> 2), c = kt * 8 + (L & 3);
    float4 v;
    v.x = tf32_rna(g_X[r * AD + c]);
    v.y = tf32_rna(g_X[(r + 8) * AD + c]);
    v.z = tf32_rna(g_X[r * AD + c + 4]);
    v.w = tf32_rna(g_X[(r + 8) * AD + c + 4]);
    *reinterpret_cast<float4*>(g_Xp + (size_t)idx * 4) = v;
}

__global__ void anAperm_kernel() {
    int idx = blockIdx.x * 256 + threadIdx.x;
    int L = idx & 31, kt = (idx >> 5) % 96, mt = idx / (32 * 96);
    int r = mt * 16 + (L >> 2), c = kt * 8 + (L & 3);
    float4 v;
    v.x = tf32_rna(g_anorm[r * DD + c]);
    v.y = tf32_rna(g_anorm[(r + 8) * DD + c]);
    v.z = tf32_rna(g_anorm[r * DD + c + 4]);
    v.w = tf32_rna(g_anorm[(r + 8) * DD + c + 4]);
    *reinterpret_cast<float4*>(g_anAp + (size_t)idx * 4) = v;
}

__global__ void yBperm_kernel(const float* __restrict__ y) {
    int idx = blockIdx.x * 256 + threadIdx.x;
    int L = idx & 31, kt = (idx >> 5) % 96, nt = idx / (32 * 96);
    int n = nt * 8 + (L >> 2), k = kt * 8 + (L & 3);
    float iv = g_invyn[n];
    float2 v;
    v.x = tf32_rna(y[(size_t)n * DD + k] * iv);
    v.y = tf32_rna(y[(size_t)n * DD + k + 4] * iv);
    *reinterpret_cast<float2*>(g_yp + (size_t)idx * 2) = v;
}

__global__ void cAperm_kernel() {
    int idx = blockIdx.x * 256 + threadIdx.x;
    int L = idx & 31, kt = (idx >> 5) & 127, mt = idx >> 12;
    int r = mt * 16 + (L >> 2), ca = kt * 8 + (L & 3);
    float4 v;
    v.x = tf32_rna(g_c[(size_t)ca * BD + r]);
    v.y = tf32_rna(g_c[(size_t)ca * BD + r + 8]);
    v.z = tf32_rna(g_c[(size_t)(ca + 4) * BD + r]);
    v.w = tf32_rna(g_c[(size_t)(ca + 4) * BD + r + 8]);
    *reinterpret_cast<float4*>(g_cTp + (size_t)idx * 4) = v;
}

__global__ void anBperm_kernel() {
    int idx = blockIdx.x * 256 + threadIdx.x;
    int L = idx & 31, kt = (idx >> 5) & 127, nt = idx >> 12;
    int n = nt * 8 + (L >> 2), k = kt * 8 + (L & 3);
    float2 v;
    v.x = tf32_rna(g_anorm[(size_t)k * DD + n]);
    v.y = tf32_rna(g_anorm[(size_t)(k + 4) * DD + n]);
    *reinterpret_cast<float2*>(g_anTp + (size_t)idx * 2) = v;
}

__global__ void init_kernel() {
    size_t i4 = ((size_t)blockIdx.x * 256 + threadIdx.x) * 4;
    int a = (int)(i4 / BD);
    float rs = g_rsx[a] * (1.0f / AD);
    float4 q4 = *reinterpret_cast<const float4*>(g_q + i4);
    float4 g;
    g.x = rs - q4.x; g.y = rs - q4.y; g.z = rs - q4.z; g.w = rs - q4.w;
    *reinterpret_cast<float4*>(g_grad + i4) = g;
    float4 cc = make_float4(1.0f / AD, 1.0f / AD, 1.0f / AD, 1.0f / AD);
    *reinterpret_cast<float4*>(g_c + i4) = cc;
}

// =====================================================================
// fp32 SIMT GEMM (X only — full precision)
// =====================================================================
template <bool AKM, bool BKM, int SCALE>
__global__ void __launch_bounds__(256) gemm_kernel(
    const float* __restrict__ A, const float* __restrict__ B, float* __restrict__ C,
    int M, int N, int K, int lda, int ldb, int ldc, const float* __restrict__ scale)
{
    __shared__ float As[16][132];
    __shared__ float Bs[16][132];
    const int tid = threadIdx.x;
    const int tx = tid & 15, ty = tid >> 4;
    const int m0 = blockIdx.y * 128, n0 = blockIdx.x * 128;
    float acc[8][8];
#pragma unroll
    for (int i = 0; i < 8; i++)
#pragma unroll
        for (int j = 0; j < 8; j++) acc[i][j] = 0.f;

    for (int k0 = 0; k0 < K; k0 += 16) {
#pragma unroll
        for (int i = 0; i < 2; i++) {
            int lin = tid + i * 256;
            if (AKM) {
                int kk = lin >> 5, mm = (lin & 31) << 2;
                float4 v = *reinterpret_cast<const float4*>(A + (size_t)(k0 + kk) * lda + (m0 + mm));
                *reinterpret_cast<float4*>(&As[kk][mm]) = v;
            } else {
                int mm = lin >> 2, kk = (lin & 3) << 2;
                float4 v = *reinterpret_cast<const float4*>(A + (size_t)(m0 + mm) * lda + (k0 + kk));
                As[kk + 0][mm] = v.x; As[kk + 1][mm] = v.y;
                As[kk + 2][mm] = v.z; As[kk + 3][mm] = v.w;
            }
        }
#pragma unroll
        for (int i = 0; i < 2; i++) {
            int lin = tid + i * 256;
            if (BKM) {
                int kk = lin >> 5, nn = (lin & 31) << 2;
                float4 v = *reinterpret_cast<const float4*>(B + (size_t)(k0 + kk) * ldb + (n0 + nn));
                *reinterpret_cast<float4*>(&Bs[kk][nn]) = v;
            } else {
                int nn = lin >> 2, kk = (lin & 3) << 2;
                float4 v = *reinterpret_cast<const float4*>(B + (size_t)(n0 + nn) * ldb + (k0 + kk));
                Bs[kk + 0][nn] = v.x; Bs[kk + 1][nn] = v.y;
                Bs[kk + 2][nn] = v.z; Bs[kk + 3][nn] = v.w;
            }
        }
        __syncthreads();
#pragma unroll
        for (int k = 0; k < 16; k++) {
            float af[8], bf[8];
            *reinterpret_cast<float4*>(&af[0]) = *reinterpret_cast<float4*>(&As[k][ty * 8]);
            *reinterpret_cast<float4*>(&af[4]) = *reinterpret_cast<float4*>(&As[k][ty * 8 + 4]);
            *reinterpret_cast<float4*>(&bf[0]) = *reinterpret_cast<float4*>(&Bs[k][tx * 8]);
            *reinterpret_cast<float4*>(&bf[4]) = *reinterpret_cast<float4*>(&Bs[k][tx * 8 + 4]);
#pragma unroll
            for (int i = 0; i < 8; i++)
#pragma unroll
                for (int j = 0; j < 8; j++) acc[i][j] += af[i] * bf[j];
        }
        __syncthreads();
    }
#pragma unroll
    for (int i = 0; i < 8; i++) {
        int m = m0 + ty * 8 + i;
        float rowf = (SCALE == 2) ? scale[m] : 1.f;
#pragma unroll
        for (int j = 0; j < 8; j++) {
            float f = (SCALE == 1) ? scale[n0 + tx * 8 + j] : rowf;
            C[(size_t)m * ldc + n0 + tx * 8 + j] = acc[i][j] * f;
        }
    }
}

// =====================================================================
// generic tf32 mma GEMM (fragment-order operands, from R11)
// =====================================================================
#define A_CH 16384
#define B_CH 16384
#define SMEM_DYN (2 * (A_CH + B_CH))

template <int SCALE>
__global__ void __launch_bounds__(256, 2) mma_gemm_kernel(
    const float* __restrict__ Af, const float* __restrict__ Bf,
    float* __restrict__ C, int kt_tot, int nck, int ldc,
    const float* __restrict__ scale)
{
    extern __shared__ char smc[];
    const uint32_t sb = smem_u32(smc);
    const int tid = threadIdx.x;
    const int wid = tid >> 5, lane = tid & 31;
    const int m0 = blockIdx.y * 128, n0 = blockIdx.x * 128;
    const int mt0 = m0 >> 4;
    const int nt0 = n0 >> 3;

    float acc[2][8][4];
#pragma unroll
    for (int i = 0; i < 2; i++)
#pragma unroll
        for (int j = 0; j < 8; j++)
#pragma unroll
            for (int v = 0; v < 4; v++) acc[i][j][v] = 0.f;

#define PREFETCH(CK, BUF) do { \
    const int _kt0 = (CK) * 4; \
    _Pragma("unroll") \
    for (int s = 0; s < 4; s++) { \
        int idx = tid + s * 256; \
        int mtl = idx >> 7, remA = idx & 127; \
        const float* srcA = Af + ((size_t)(mt0 + mtl) * kt_tot + _kt0) * 128 + remA * 4; \
        CP16(sb + (BUF) * (A_CH + B_CH) + (mtl * 128 + remA) * 16, srcA); \
        int ntl = idx >> 6, remB = idx & 63; \
        const float* srcB = Bf + ((size_t)(nt0 + ntl) * kt_tot + _kt0) * 64 + remB * 4; \
        CP16(sb + (BUF) * (A_CH + B_CH) + A_CH + (ntl * 64 + remB) * 16, srcB); \
    } \
    CP_COMMIT(); } while (0)

    PREFETCH(0, 0);

    const int wm = (wid >> 1) * 2;
    const int wn = (wid & 1) * 8;

    for (int ck = 0; ck < nck; ck++) {
        const int buf = ck & 1;
        if (ck + 1 < nck) {
            PREFETCH(ck + 1, (ck + 1) & 1);
            CP_WAIT(1);
        } else {
            CP_WAIT(0);
        }
        __syncthreads();

        const char* Abase = smc + buf * (A_CH + B_CH);
        const char* Bbase = Abase + A_CH;

#pragma unroll
        for (int ktl = 0; ktl < 4; ktl++) {
            uint32_t afr[2][4];
#pragma unroll
            for (int i = 0; i < 2; i++) {
                uint4 v = *reinterpret_cast<const uint4*>(
                    Abase + (((wm + i) * 4 + ktl) * 32 + lane) * 16);
                afr[i][0] = v.x; afr[i][1] = v.y; afr[i][2] = v.z; afr[i][3] = v.w;
            }
            uint32_t bfr[8][2];
#pragma unroll
            for (int j = 0; j < 8; j++) {
                uint2 v = *reinterpret_cast<const uint2*>(
                    Bbase + (((wn + j) * 4 + ktl) * 32 + lane) * 8);
                bfr[j][0] = v.x; bfr[j][1] = v.y;
            }
#pragma unroll
            for (int i = 0; i < 2; i++)
#pragma unroll
                for (int j = 0; j < 8; j++)
                    mma_tf32_16n8k8(acc[i][j], afr[i], bfr[j]);
        }
        __syncthreads();
    }
#undef PREFETCH

    const int grp = lane >> 2, q4 = lane & 3;
#pragma unroll
    for (int i = 0; i < 2; i++) {
        int row = m0 + (wid >> 1) * 32 + i * 16 + grp;
        float s0 = (SCALE == 2) ? scale[row] : 1.f;
        float s1 = (SCALE == 2) ? scale[row + 8] : 1.f;
#pragma unroll
        for (int j = 0; j < 8; j++) {
            int col = n0 + (wid & 1) * 64 + j * 8 + q4 * 2;
            *reinterpret_cast<float2*>(C + (size_t)row * ldc + col) =
                make_float2(acc[i][j][0] * s0, acc[i][j][1] * s0);
            *reinterpret_cast<float2*>(C + (size_t)(row + 8) * ldc + col) =
                make_float2(acc[i][j][2] * s1, acc[i][j][3] * s1);
        }
    }
}

// =====================================================================
// argmin kernels
// =====================================================================
__global__ void __launch_bounds__(256) argmin_full_kernel() {
    const int a = blockIdx.x;
    const float* row = g_grad + (size_t)a * BD;
    unsigned long long best = ~0ull;
    for (int it = 0; it < 16; it++) {
        int j = threadIdx.x * 4 + it * 1024;
        float4 v = *reinterpret_cast<const float4*>(row + j);
        unsigned long long k0 = packmin(v.x, j);
        unsigned long long k1 = packmin(v.y, j + 1);
        unsigned long long k2 = packmin(v.z, j + 2);
        unsigned long long k3 = packmin(v.w, j + 3);
        if (k1 < k0) k0 = k1;
        if (k3 < k2) k2 = k3;
        if (k2 < k0) k0 = k2;
        if (k0 < best) best = k0;
    }
    __shared__ unsigned long long sk[256];
    sk[threadIdx.x] = best;
    __syncthreads();
    for (int o = 128; o; o >>= 1) {
        if (threadIdx.x < o && sk[threadIdx.x + o] < sk[threadIdx.x])
            sk[threadIdx.x] = sk[threadIdx.x + o];
        __syncthreads();
    }
    if (!threadIdx.x) g_amin[a] = (int)(sk[0] & 0xFFFFFFFFu);
}

__global__ void __launch_bounds__(256) argmin_parts_kernel() {
    const int wid = threadIdx.x >> 5, lane = threadIdx.x & 31;
    const int a = blockIdx.x * 8 + wid;
    unsigned long long best = ~0ull;
#pragma unroll
    for (int k = 0; k < NBLK / 32; k++) {
        unsigned long long v = g_minp[(size_t)a * NBLK + lane + k * 32];
        if (v < best) best = v;
    }
#pragma unroll
    for (int o = 16; o; o >>= 1) {
        unsigned long long v = __shfl_down_sync(0xffffffffu, best, o);
        if (v < best) best = v;
    }
    if (!lane) g_amin[a] = (int)(best & 0xFFFFFFFFu);
}

// =====================================================================
// selection list
// =====================================================================
__device__ __forceinline__ void build_sel_list(
    const int* amin_s, int j0, int* sel_a, int* sel_j, int* nsel_s,
    int tid)
{
    if (tid < 32) {
        int cnt = 0;
        for (int base = 0; base < AD; base += 32) {
            int a = base + tid;
            int jm = amin_s[a];
            bool mt = (jm >= j0 && jm < j0 + 64);
            unsigned mask = __ballot_sync(0xffffffffu, mt);
            if (mt) {
                int p = cnt + __popc(mask & ((1u << tid) - 1u));
                sel_a[p] = a; sel_j[p] = jm;
            }
            cnt += __popc(mask);
        }
        if (tid == 0) *nsel_s = cnt;
    }
}

// =====================================================================
// step-0 dense reduce (R9/R11 version): num_j + denom partials
// =====================================================================
__global__ void __launch_bounds__(256) nd_reduce_kernel() {
    const int tid = threadIdx.x, tx = tid & 15, ty = tid >> 4;
    const int j0 = blockIdx.x * 64, jb = j0 + tx * 4;
    __shared__ int amin_s[AD];
    __shared__ int sel_a[AD], sel_j[AD], nsel_s;
    for (int a = tid; a < AD; a += 256) amin_s[a] = g_amin[a];
    __syncthreads();
    build_sel_list(amin_s, j0, sel_a, sel_j, &nsel_s, tid);
    __syncthreads();
    const int ns = nsel_s;

    float4 num4 = {0, 0, 0, 0}, den4 = {0, 0, 0, 0};
    for (int a = ty; a < AD; a += 16) {
        size_t idx = (size_t)a * BD + jb;
        float4 cc = *reinterpret_cast<const float4*>(g_c + idx);
        float4 gg = *reinterpret_cast<const float4*>(g_grad + idx);
        float4 qq = *reinterpret_cast<const float4*>(g_q + idx);
        float4 S = {0, 0, 0, 0};
        for (int e = 0; e < ns; e++) {
            float xv = g_X[a * AD + sel_a[e]];
            int d = sel_j[e] - jb;
            S.x += (d == 0) ? xv : 0.f;
            S.y += (d == 1) ? xv : 0.f;
            S.z += (d == 2) ? xv : 0.f;
            S.w += (d == 3) ? xv : 0.f;
        }
        int am = amin_s[a];
        float4 dd, xd;
        dd.x = ((am == jb + 0) ? 1.f : 0.f) - cc.x;
        dd.y = ((am == jb + 1) ? 1.f : 0.f) - cc.y;
        dd.z = ((am == jb + 2) ? 1.f : 0.f) - cc.z;
        dd.w = ((am == jb + 3) ? 1.f : 0.f) - cc.w;
        xd.x = S.x - gg.x - qq.x; xd.y = S.y - gg.y - qq.y;
        xd.z = S.z - gg.z - qq.z; xd.w = S.w - gg.w - qq.w;
        num4.x += dd.x * gg.x; num4.y += dd.y * gg.y;
        num4.z += dd.z * gg.z; num4.w += dd.w * gg.w;
        den4.x += dd.x * xd.x; den4.y += dd.y * xd.y;
        den4.z += dd.z * xd.z; den4.w += dd.w * xd.w;
    }
    __shared__ float4 rn[16][17], rd[16][17];
    __shared__ float colden[16];
    rn[ty][tx] = num4; rd[ty][tx] = den4;
    __syncthreads();
    if (ty == 0) {
        float4 n = rn[0][tx], d = rd[0][tx];
        for (int t = 1; t < 16; t++) {
            float4 n2 = rn[t][tx], d2 = rd[t][tx];
            n.x += n2.x; n.y += n2.y; n.z += n2.z; n.w += n2.w;
            d.x += d2.x; d.y += d2.y; d.z += d2.z; d.w += d2.w;
        }
        *reinterpret_cast<float4*>(g_num + jb) = n;
        colden[tx] = d.x + d.y + d.z + d.w;
    }
    __syncthreads();
    if (tid == 0) {
        float s = 0.f;
        for (int t = 0; t < 16; t++) s += colden[t];
        g_denpart[blockIdx.x] = s;
    }
}

// lam from dense denpart (step 0)
__global__ void __launch_bounds__(256) lam0_kernel() {
    __shared__ float red[256];
    const int tid = threadIdx.x;
    red[tid] = g_denpart[tid];
    __syncthreads();
    for (int o = 128; o; o >>= 1) {
        if (tid < o) red[tid] += red[tid + o];
        __syncthreads();
    }
    const float denom = red[0] + EPSC;
    int j = blockIdx.x * 256 + tid;
    g_lam[j] = fminf(fmaxf(-g_num[j] / denom, 0.f), 1.f);
}

// =====================================================================
// fused nondiff update: applies lam, writes c/grad, emits argmin partials
// AND dense column sums colcg = Σ c_new·g_new, colcq = Σ c_new·q.
// =====================================================================
__global__ void __launch_bounds__(256) nd_update_kernel() {
    const int tid = threadIdx.x, tx = tid & 15, ty = tid >> 4;
    const int j0 = blockIdx.x * 64, jb = j0 + tx * 4;
    __shared__ int amin_s[AD];
    __shared__ int sel_a[AD], sel_j[AD], nsel_s;
    for (int a = tid; a < AD; a += 256) amin_s[a] = g_amin[a];
    __syncthreads();
    build_sel_list(amin_s, j0, sel_a, sel_j, &nsel_s, tid);
    __syncthreads();
    const int ns = nsel_s;
    const float4 lam = *reinterpret_cast<const float4*>(g_lam + jb);

    float4 cg4 = {0, 0, 0, 0}, cq4 = {0, 0, 0, 0};
    for (int a = ty; a < AD; a += 16) {
        size_t idx = (size_t)a * BD + jb;
        float4 cc = *reinterpret_cast<const float4*>(g_c + idx);
        float4 gg = *reinterpret_cast<const float4*>(g_grad + idx);
        float4 qq = *reinterpret_cast<const float4*>(g_q + idx);
        float4 S = {0, 0, 0, 0};
        for (int e = 0; e < ns; e++) {
            float xv = g_X[a * AD + sel_a[e]];
            int d = sel_j[e] - jb;
            S.x += (d == 0) ? xv : 0.f;
            S.y += (d == 1) ? xv : 0.f;
            S.z += (d == 2) ? xv : 0.f;
            S.w += (d == 3) ? xv : 0.f;
        }
        int am = amin_s[a];
        float4 dd, xd, c2, g2;
        dd.x = ((am == jb + 0) ? 1.f : 0.f) - cc.x;
        dd.y = ((am == jb + 1) ? 1.f : 0.f) - cc.y;
        dd.z = ((am == jb + 2) ? 1.f : 0.f) - cc.z;
        dd.w = ((am == jb + 3) ? 1.f : 0.f) - cc.w;
        xd.x = S.x - gg.x - qq.x; xd.y = S.y - gg.y - qq.y;
        xd.z = S.z - gg.z - qq.z; xd.w = S.w - gg.w - qq.w;
        c2.x = cc.x + lam.x * dd.x; c2.y = cc.y + lam.y * dd.y;
        c2.z = cc.z + lam.z * dd.z; c2.w = cc.w + lam.w * dd.w;
        g2.x = gg.x + lam.x * xd.x; g2.y = gg.y + lam.y * xd.y;
        g2.z = gg.z + lam.z * xd.z; g2.w = gg.w + lam.w * xd.w;
        *reinterpret_cast<float4*>(g_c + idx)    = c2;
        *reinterpret_cast<float4*>(g_grad + idx) = g2;

        cg4.x += c2.x * g2.x; cg4.y += c2.y * g2.y;
        cg4.z += c2.z * g2.z; cg4.w += c2.w * g2.w;
        cq4.x += c2.x * qq.x; cq4.y += c2.y * qq.y;
        cq4.z += c2.z * qq.z; cq4.w += c2.w * qq.w;

        unsigned long long best = packmin(g2.x, jb);
        unsigned long long k1 = packmin(g2.y, jb + 1);
        unsigned long long k2 = packmin(g2.z, jb + 2);
        unsigned long long k3 = packmin(g2.w, jb + 3);
        if (k1 < best) best = k1;
        if (k2 < best) best = k2;
        if (k3 < best) best = k3;
#pragma unroll
        for (int o = 8; o; o >>= 1) {
            unsigned long long v = __shfl_down_sync(0xffffffffu, best, o, 16);
            if (v < best) best = v;
        }
        if (tx == 0) g_minp[(size_t)a * NBLK + blockIdx.x] = best;
    }
    __shared__ float4 rg[16][17], rq[16][17];
    rg[ty][tx] = cg4; rq[ty][tx] = cq4;
    __syncthreads();
    if (ty == 0) {
        float4 cg = rg[0][tx], cq = rq[0][tx];
        for (int t = 1; t < 16; t++) {
            float4 a2 = rg[t][tx], b2 = rq[t][tx];
            cg.x += a2.x; cg.y += a2.y; cg.z += a2.z; cg.w += a2.w;
            cq.x += b2.x; cq.y += b2.y; cq.z += b2.z; cq.w += b2.w;
        }
        *reinterpret_cast<float4*>(g_colcg + jb) = cg;
        *reinterpret_cast<float4*>(g_colcq + jb) = cq;
    }
}

// =====================================================================
// sparse num/den path (steps 1..29)
// gather: per atom a with j = amin[a]:
//   gp[a] = grad[a][j], qp[a] = q[a][j], pp[a] = Σ_{a': amin[a']=j} X[a][a']
// =====================================================================
__global__ void __launch_bounds__(128) gather_kernel() {
    __shared__ int amin_s[AD];
    __shared__ float red[128];
    const int a = blockIdx.x, tid = threadIdx.x;
    for (int i = tid; i < AD; i += 128) amin_s[i] = g_amin[i];
    __syncthreads();
    const int j = amin_s[a];
    float p = 0.f;
    const float* xrow = g_X + a * AD;
    for (int ap = tid; ap < AD; ap += 128)
        if (amin_s[ap] == j) p += xrow[ap];
    red[tid] = p;
    __syncthreads();
    for (int o = 64; o; o >>= 1) {
        if (tid < o) red[tid] += red[tid + o];
        __syncthreads();
    }
    if (tid == 0) {
        g_pp[a] = red[0];
        g_gp[a] = g_grad[(size_t)a * BD + j];
        g_qp[a] = g_q[(size_t)a * BD + j];
    }
}

// num_j = G_j - colcg_j ; den_j = P_j - 2(G_j + Q_j) + colcg_j + colcq_j
__global__ void __launch_bounds__(256) numden_kernel() {
    __shared__ int amin_s[AD];
    __shared__ float gp[AD], qp[AD], pp[AD];
    const int tid = threadIdx.x;
    for (int i = tid; i < AD; i += 256) {
        amin_s[i] = g_amin[i];
        gp[i] = g_gp[i]; qp[i] = g_qp[i]; pp[i] = g_pp[i];
    }
    __syncthreads();
    const int j = blockIdx.x * 256 + tid;
    float G = 0.f, Q = 0.f, P = 0.f;
    for (int e = 0; e < AD; e++) {
        bool m = (amin_s[e] == j);
        G += m ? gp[e] : 0.f;
        Q += m ? qp[e] : 0.f;
        P += m ? pp[e] : 0.f;
    }
    float ccg = g_colcg[j], ccq = g_colcq[j];
    g_num[j] = G - ccg;
    g_den[j] = P - 2.f * (G + Q) + ccg + ccq;
}

// denom = Σ_j den_j (deterministic; identical in every block), lam_j
__global__ void __launch_bounds__(256) lam_kernel() {
    __shared__ float red[256];
    const int tid = threadIdx.x;
    float s = 0.f;
    for (int i = 0; i < 64; i++) s += g_den[tid * 64 + i];
    red[tid] = s;
    __syncthreads();
    for (int o = 128; o; o >>= 1) {
        if (tid < o) red[tid] += red[tid + o];
        __syncthreads();
    }
    const float denom = red[0] + EPSC;
    int j = blockIdx.x * 256 + tid;
    g_lam[j] = fminf(fmaxf(-g_num[j] / denom, 0.f), 1.f);
}

// =====================================================================
// diff phase (unchanged from R11)
// =====================================================================
__global__ void __launch_bounds__(256) softmaxT_kernel() {
    const int tid = threadIdx.x, tx = tid & 15, ty = tid >> 4;
    const int j0 = blockIdx.x * 64, jb = j0 + tx * 4;

    float4 m4 = {-INFINITY, -INFINITY, -INFINITY, -INFINITY};
    float4 s4 = {0, 0, 0, 0};
    for (int a = ty; a < AD; a += 16) {
        float4 g = *reinterpret_cast<const float4*>(g_grad + (size_t)a * BD + jb);
        float v;
        v = -TEMPC * g.x; if (v > m4.x) { s4.x = s4.x * expf(m4.x - v) + 1.f; m4.x = v; } else s4.x += expf(v - m4.x);
        v = -TEMPC * g.y; if (v > m4.y) { s4.y = s4.y * expf(m4.y - v) + 1.f; m4.y = v; } else s4.y += expf(v - m4.y);
        v = -TEMPC * g.z; if (v > m4.z) { s4.z = s4.z * expf(m4.z - v) + 1.f; m4.z = v; } else s4.z += expf(v - m4.z);
        v = -TEMPC * g.w; if (v > m4.w) { s4.w = s4.w * expf(m4.w - v) + 1.f; m4.w = v; } else s4.w += expf(v - m4.w);
    }
    __shared__ float4 mm[16][17], ss[16][17];
    __shared__ float4 fm[16], fsinv[16];
    mm[ty][tx] = m4; ss[ty][tx] = s4;
    __syncthreads();
    if (ty == 0) {
        float4 M = mm[0][tx], S = ss[0][tx];
        for (int t = 1; t < 16; t++) {
            float4 m2 = mm[t][tx], s2 = ss[t][tx];
            float Mn;
            Mn = fmaxf(M.x, m2.x); S.x = S.x * expf(M.x - Mn) + s2.x * expf(m2.x - Mn); M.x = Mn;
            Mn = fmaxf(M.y, m2.y); S.y = S.y * expf(M.y - Mn) + s2.y * expf(m2.y - Mn); M.y = Mn;
            Mn = fmaxf(M.z, m2.z); S.z = S.z * expf(M.z - Mn) + s2.z * expf(m2.z - Mn); M.z = Mn;
            Mn = fmaxf(M.w, m2.w); S.w = S.w * expf(M.w - Mn) + s2.w * expf(m2.w - Mn); M.w = Mn;
        }
        fm[tx] = M;
        fsinv[tx] = make_float4(1.f / S.x, 1.f / S.y, 1.f / S.z, 1.f / S.w);
    }
    __syncthreads();
    const float4 M4 = fm[tx];
    const float4 I4 = fsinv[tx];

    __shared__ float tile[32][68];
    const int L = tid & 31, nt = tid >> 5;
    for (int at = 0; at < 32; at++) {
        const int a0 = at * 32;
#pragma unroll
        for (int half = 0; half < 2; half++) {
            int aa = ty + half * 16;
            size_t idx = (size_t)(a0 + aa) * BD + jb;
            float4 g = *reinterpret_cast<const float4*>(g_grad + idx);
            float4 e;
            e.x = expf(-TEMPC * g.x - M4.x) * I4.x;
            e.y = expf(-TEMPC * g.y - M4.y) * I4.y;
            e.z = expf(-TEMPC * g.z - M4.z) * I4.z;
            e.w = expf(-TEMPC * g.w - M4.w) * I4.w;
            *reinterpret_cast<float4*>(g_sm + idx) = e;
            tile[aa][tx * 4 + 0] = e.x;
            tile[aa][tx * 4 + 1] = e.y;
            tile[aa][tx * 4 + 2] = e.z;
            tile[aa][tx * 4 + 3] = e.w;
        }
        __syncthreads();
#pragma unroll
        for (int kt = 0; kt < 4; kt++) {
            float v0 = tile[kt * 8 + (L & 3)][nt * 8 + (L >> 2)];
            float v1 = tile[kt * 8 + (L & 3) + 4][nt * 8 + (L >> 2)];
            size_t o = (((size_t)(j0 / 8 + nt) * 128 + (at * 4 + kt)) * 32 + L) * 2;
            *reinterpret_cast<float2*>(g_smTp + o) =
                make_float2(tf32_rna(v0), tf32_rna(v1));
        }
        __syncthreads();
    }
}

__global__ void __launch_bounds__(256) d_reduce_kernel() {
    const int tid = threadIdx.x, tx = tid & 15, ty = tid >> 4;
    const int jb = blockIdx.x * 64 + tx * 4;
    float4 num4 = {0, 0, 0, 0}, den4 = {0, 0, 0, 0};
    for (int a = ty; a < AD; a += 16) {
        size_t idx = (size_t)a * BD + jb;
        float4 sm = *reinterpret_cast<const float4*>(g_sm + idx);
        float4 cc = *reinterpret_cast<const float4*>(g_c + idx);
        float4 xs = *reinterpret_cast<const float4*>(g_xsm + idx);
        float4 gg = *reinterpret_cast<const float4*>(g_grad + idx);
        float4 qq = *reinterpret_cast<const float4*>(g_q + idx);
        float4 dd, xd;
        dd.x = sm.x - cc.x; dd.y = sm.y - cc.y; dd.z = sm.z - cc.z; dd.w = sm.w - cc.w;
        xd.x = xs.x - gg.x - qq.x; xd.y = xs.y - gg.y - qq.y;
        xd.z = xs.z - gg.z - qq.z; xd.w = xs.w - gg.w - qq.w;
        num4.x += dd.x * gg.x; num4.y += dd.y * gg.y;
        num4.z += dd.z * gg.z; num4.w += dd.w * gg.w;
        den4.x += dd.x * xd.x; den4.y += dd.y * xd.y;
        den4.z += dd.z * xd.z; den4.w += dd.w * xd.w;
    }
    __shared__ float4 rn[16][17], rd[16][17];
    __shared__ float colden[16];
    rn[ty][tx] = num4; rd[ty][tx] = den4;
    __syncthreads();
    if (ty == 0) {
        float4 n = rn[0][tx], d = rd[0][tx];
        for (int t = 1; t < 16; t++) {
            float4 n2 = rn[t][tx], d2 = rd[t][tx];
            n.x += n2.x; n.y += n2.y; n.z += n2.z; n.w += n2.w;
            d.x += d2.x; d.y += d2.y; d.z += d2.z; d.w += d2.w;
        }
        *reinterpret_cast<float4*>(g_num + jb) = n;
        colden[tx] = d.x + d.y + d.z + d.w;
    }
    __syncthreads();
    if (tid == 0) {
        float s = 0.f;
        for (int t = 0; t < 16; t++) s += colden[t];
        g_denpart[blockIdx.x] = s;
    }
}

template <bool LAST>
__global__ void __launch_bounds__(256) d_update_kernel() {
    const int tid = threadIdx.x, tx = tid & 15, ty = tid >> 4;
    const int jb = blockIdx.x * 64 + tx * 4;
    __shared__ float red[256];
    red[tid] = g_denpart[tid];
    __syncthreads();
    for (int o = 128; o; o >>= 1) {
        if (tid < o) red[tid] += red[tid + o];
        __syncthreads();
    }
    const float denom = red[0] + EPSC;
    float4 nm = *reinterpret_cast<const float4*>(g_num + jb);
    float4 lam;
    lam.x = fminf(fmaxf(-nm.x / denom, 0.f), 1.f);
    lam.y = fminf(fmaxf(-nm.y / denom, 0.f), 1.f);
    lam.z = fminf(fmaxf(-nm.z / denom, 0.f), 1.f);
    lam.w = fminf(fmaxf(-nm.w / denom, 0.f), 1.f);
    for (int a = ty; a < AD; a += 16) {
        size_t idx = (size_t)a * BD + jb;
        float4 sm = *reinterpret_cast<const float4*>(g_sm + idx);
        float4 cc = *reinterpret_cast<const float4*>(g_c + idx);
        float4 c2;
        c2.x = cc.x + lam.x * (sm.x - cc.x);
        c2.y = cc.y + lam.y * (sm.y - cc.y);
        c2.z = cc.z + lam.z * (sm.z - cc.z);
        c2.w = cc.w + lam.w * (sm.w - cc.w);
        *reinterpret_cast<float4*>(g_c + idx) = c2;
        if (!LAST) {
            float4 xs = *reinterpret_cast<const float4*>(g_xsm + idx);
            float4 gg = *reinterpret_cast<const float4*>(g_grad + idx);
            float4 qq = *reinterpret_cast<const float4*>(g_q + idx);
            float4 g2;
            g2.x = gg.x + lam.x * (xs.x - gg.x - qq.x);
            g2.y = gg.y + lam.y * (xs.y - gg.y - qq.y);
            g2.z = gg.z + lam.z * (xs.z - gg.z - qq.z);
            g2.w = gg.w + lam.w * (xs.w - gg.w - qq.w);
            *reinterpret_cast<float4*>(g_grad + idx) = g2;
        }
    }
}

// =====================================================================
// host launcher
// =====================================================================
extern "C" void kernel_launch(void* const* d_in, const int* in_sizes, int n_in,
                              void* d_out, int out_size)
{
    const float* y     = (const float*)d_in[0];
    const float* atoms = (const float*)d_in[1];
    float* out = (float*)d_out;

    float *p_anorm, *p_X, *p_Xp, *p_anAp, *p_yp, *p_cTp, *p_anTp, *p_q, *p_xsm, *p_smTp, *p_ynorm;
    cudaGetSymbolAddress((void**)&p_anorm, g_anorm);
    cudaGetSymbolAddress((void**)&p_X,     g_X);
    cudaGetSymbolAddress((void**)&p_Xp,    g_Xp);
    cudaGetSymbolAddress((void**)&p_anAp,  g_anAp);
    cudaGetSymbolAddress((void**)&p_yp,    g_yp);
    cudaGetSymbolAddress((void**)&p_cTp,   g_cTp);
    cudaGetSymbolAddress((void**)&p_anTp,  g_anTp);
    cudaGetSymbolAddress((void**)&p_q,     g_q);
    cudaGetSymbolAddress((void**)&p_xsm,   g_xsm);
    cudaGetSymbolAddress((void**)&p_smTp,  g_smTp);
    cudaGetSymbolAddress((void**)&p_ynorm, g_ynorm);

    cudaFuncSetAttribute(mma_gemm_kernel<0>,
                         cudaFuncAttributeMaxDynamicSharedMemorySize, SMEM_DYN);
    cudaFuncSetAttribute(mma_gemm_kernel<2>,
                         cudaFuncAttributeMaxDynamicSharedMemorySize, SMEM_DYN);

    ynorm_kernel<<<BD / 8, 256>>>(y);
    anorm_kernel<<<AD, 256>>>(atoms);

    gemm_kernel<false, false, 0><<<dim3(AD / 128, AD / 128), 256>>>(
        p_anorm, p_anorm, p_X, AD, AD, DD, DD, DD, AD, nullptr);
    rowsumX_kernel<<<AD / 8, 256>>>();
    xperm_kernel<<<1024, 256>>>();

    anAperm_kernel<<<768, 256>>>();
    yBperm_kernel<<<24576, 256>>>(y);
    mma_gemm_kernel<0><<<dim3(BD / 128, AD / 128), 256, SMEM_DYN>>>(
        p_anAp, p_yp, p_q, 96, 24, BD, nullptr);

    init_kernel<<<(AD * BD) / 1024, 256>>>();

    // nondiff: dense reduce once (step 0), then sparse num/den path
    argmin_full_kernel<<<AD, 256>>>();
    nd_reduce_kernel<<<NBLK, 256>>>();
    lam0_kernel<<<BD / 256, 256>>>();
    for (int s = 0; s < NONDIFF; s++) {
        nd_update_kernel<<<NBLK, 256>>>();
        if (s + 1 < NONDIFF) {
            argmin_parts_kernel<<<AD / 8, 256>>>();
            gather_kernel<<<AD, 128>>>();
            numden_kernel<<<BD / 256, 256>>>();
            lam_kernel<<<BD / 256, 256>>>();
        }
    }

    for (int s = 0; s < DIFFST; s++) {
        softmaxT_kernel<<<NBLK, 256>>>();
        mma_gemm_kernel<0><<<dim3(BD / 128, AD / 128), 256, SMEM_DYN>>>(
            p_Xp, p_smTp, p_xsm, 128, 32, BD, nullptr);
        d_reduce_kernel<<<NBLK, 256>>>();
        if (s + 1 < DIFFST) d_update_kernel<false><<<NBLK, 256>>>();
        else                d_update_kernel<true ><<<NBLK, 256>>>();
    }

    cAperm_kernel<<<16384, 256>>>();
    anBperm_kernel<<<1536, 256>>>();
    mma_gemm_kernel<2><<<dim3(DD / 128, BD / 128), 256, SMEM_DYN>>>(
        p_cTp, p_anTp, out, 128, 32, DD, p_ynorm);
}

// round 15
// speedup vs baseline: 5.1392x; 1.0984x over previous
#include <cuda_runtime.h>
#include <math.h>
#include <stdint.h>

#define AD 1024
#define BD 16384
#define DD 768
#define TEMPC 100.0f
#define EPSC 1e-8f
#define NONDIFF 30
#define DIFFST 10
#define NBLK 256            /* BD / 64 column blocks */

// ---- device scratch (allocation-free: __device__ globals) ----
__device__ float g_anorm[AD * DD];
__device__ float g_X[AD * AD];
__device__ float g_Xp[AD * AD];
__device__ float g_anAp[AD * DD];
__device__ float g_yp[(size_t)BD * DD];
__device__ float g_cTp[(size_t)BD * AD];
__device__ float g_anTp[DD * AD];
__device__ float g_rsx[AD];
__device__ float g_q[AD * BD];
__device__ float g_c[AD * BD];
__device__ float g_grad[AD * BD];
__device__ float g_sm[AD * BD];
__device__ float g_smTp[(size_t)BD * AD];
__device__ float g_xsm[AD * BD];
__device__ float g_ynorm[BD];
__device__ float g_invyn[BD];
__device__ int   g_amin[AD];
__device__ float g_num[BD];
__device__ float g_den[BD];
__device__ float g_denpart[NBLK];
__device__ float g_lam[BD];
__device__ float g_colcg[BD];
__device__ float g_colcq[BD];
__device__ float g_colsg[BD];
__device__ float g_colsq[BD];
__device__ float g_psm[8 * BD];     // per-m-block partials of sum sm*xsm
__device__ float g_pcx[8 * BD];     // per-m-block partials of sum c*xsm
__device__ float g_gp[AD];
__device__ float g_qp[AD];
__device__ float g_pp[AD];
__device__ unsigned long long g_minp[AD * NBLK];

__device__ __forceinline__ float tf32_rna(float x) {
    float r;
    asm("cvt.rna.tf32.f32 %0, %1;" : "=f"(r) : "f"(x));
    return r;
}
__device__ __forceinline__ uint32_t smem_u32(const void* p) {
    uint32_t a;
    asm("{ .reg .u64 t; cvta.to.shared.u64 t, %1; cvt.u32.u64 %0, t; }" : "=r"(a) : "l"(p));
    return a;
}
__device__ __forceinline__ unsigned fenc(float v) {
    unsigned b = __float_as_uint(v);
    return b ^ ((b & 0x80000000u) ? 0xFFFFFFFFu : 0x80000000u);
}
__device__ __forceinline__ unsigned long long packmin(float v, int j) {
    return ((unsigned long long)fenc(v) << 32) | (unsigned)j;
}
#define CP16(dst, src) asm volatile("cp.async.cg.shared.global [%0], [%1], 16;" :: "r"(dst), "l"(src))
#define CP_COMMIT()    asm volatile("cp.async.commit_group;" ::: "memory")
#define CP_WAIT(n)     asm volatile("cp.async.wait_group %0;" :: "n"(n) : "memory")

__device__ __forceinline__ void mma_tf32_16n8k8(float* c, const uint32_t* a, const uint32_t* b) {
    asm volatile(
        "mma.sync.aligned.m16n8k8.row.col.f32.tf32.tf32.f32 "
        "{%0,%1,%2,%3}, {%4,%5,%6,%7}, {%8,%9}, {%0,%1,%2,%3};"
        : "+f"(c[0]), "+f"(c[1]), "+f"(c[2]), "+f"(c[3])
        : "r"(a[0]), "r"(a[1]), "r"(a[2]), "r"(a[3]), "r"(b[0]), "r"(b[1]));
}

// =====================================================================
// init kernels
// =====================================================================
__global__ void ynorm_kernel(const float* __restrict__ y) {
    int w = (blockIdx.x * blockDim.x + threadIdx.x) >> 5;
    int lane = threadIdx.x & 31;
    if (w >= BD) return;
    const float* row = y + (size_t)w * DD;
    float s = 0.f;
    for (int d = lane; d < DD; d += 32) s += fabsf(row[d]);
#pragma unroll
    for (int o = 16; o; o >>= 1) s += __shfl_xor_sync(0xffffffffu, s, o);
    if (!lane) { g_ynorm[w] = s; g_invyn[w] = 1.0f / s; }
}

__global__ void anorm_kernel(const float* __restrict__ atoms) {
    int r = blockIdx.x;
    const float* row = atoms + (size_t)r * DD;
    __shared__ float red[256];
    float s = 0.f;
    for (int d = threadIdx.x; d < DD; d += 256) s += fabsf(row[d]);
    red[threadIdx.x] = s;
    __syncthreads();
    for (int o = 128; o; o >>= 1) {
        if (threadIdx.x < o) red[threadIdx.x] += red[threadIdx.x + o];
        __syncthreads();
    }
    float nrm = red[0];
    for (int d = threadIdx.x; d < DD; d += 256)
        g_anorm[r * DD + d] = row[d] / nrm;
}

__global__ void rowsumX_kernel() {
    int w = (blockIdx.x * blockDim.x + threadIdx.x) >> 5;
    int lane = threadIdx.x & 31;
    if (w >= AD) return;
    float s = 0.f;
    for (int k = lane; k < AD; k += 32) s += g_X[w * AD + k];
#pragma unroll
    for (int o = 16; o; o >>= 1) s += __shfl_xor_sync(0xffffffffu, s, o);
    if (!lane) g_rsx[w] = s;
}

__global__ void xperm_kernel() {
    int idx = blockIdx.x * 256 + threadIdx.x;
    int L = idx & 31, kt = (idx >> 5) & 127, mt = idx >> 12;
    int r = mt * 16 + (L >> 2), c = kt * 8 + (L & 3);
    float4 v;
    v.x = tf32_rna(g_X[r * AD + c]);
    v.y = tf32_rna(g_X[(r + 8) * AD + c]);
    v.z = tf32_rna(g_X[r * AD + c + 4]);
    v.w = tf32_rna(g_X[(r + 8) * AD + c + 4]);
    *reinterpret_cast<float4*>(g_Xp + (size_t)idx * 4) = v;
}

__global__ void anAperm_kernel() {
    int idx = blockIdx.x * 256 + threadIdx.x;
    int L = idx & 31, kt = (idx >> 5) % 96, mt = idx / (32 * 96);
    int r = mt * 16 + (L >> 2), c = kt * 8 + (L & 3);
    float4 v;
    v.x = tf32_rna(g_anorm[r * DD + c]);
    v.y = tf32_rna(g_anorm[(r + 8) * DD + c]);
    v.z = tf32_rna(g_anorm[r * DD + c + 4]);
    v.w = tf32_rna(g_anorm[(r + 8) * DD + c + 4]);
    *reinterpret_cast<float4*>(g_anAp + (size_t)idx * 4) = v;
}

__global__ void yBperm_kernel(const float* __restrict__ y) {
    int idx = blockIdx.x * 256 + threadIdx.x;
    int L = idx & 31, kt = (idx >> 5) % 96, nt = idx / (32 * 96);
    int n = nt * 8 + (L >> 2), k = kt * 8 + (L & 3);
    float iv = g_invyn[n];
    float2 v;
    v.x = tf32_rna(y[(size_t)n * DD + k] * iv);
    v.y = tf32_rna(y[(size_t)n * DD + k + 4] * iv);
    *reinterpret_cast<float2*>(g_yp + (size_t)idx * 2) = v;
}

__global__ void cAperm_kernel() {
    int idx = blockIdx.x * 256 + threadIdx.x;
    int L = idx & 31, kt = (idx >> 5) & 127, mt = idx >> 12;
    int r = mt * 16 + (L >> 2), ca = kt * 8 + (L & 3);
    float4 v;
    v.x = tf32_rna(g_c[(size_t)ca * BD + r]);
    v.y = tf32_rna(g_c[(size_t)ca * BD + r + 8]);
    v.z = tf32_rna(g_c[(size_t)(ca + 4) * BD + r]);
    v.w = tf32_rna(g_c[(size_t)(ca + 4) * BD + r + 8]);
    *reinterpret_cast<float4*>(g_cTp + (size_t)idx * 4) = v;
}

__global__ void anBperm_kernel() {
    int idx = blockIdx.x * 256 + threadIdx.x;
    int L = idx & 31, kt = (idx >> 5) & 127, nt = idx >> 12;
    int n = nt * 8 + (L >> 2), k = kt * 8 + (L & 3);
    float2 v;
    v.x = tf32_rna(g_anorm[(size_t)k * DD + n]);
    v.y = tf32_rna(g_anorm[(size_t)(k + 4) * DD + n]);
    *reinterpret_cast<float2*>(g_anTp + (size_t)idx * 2) = v;
}

__global__ void init_kernel() {
    size_t i4 = ((size_t)blockIdx.x * 256 + threadIdx.x) * 4;
    int a = (int)(i4 / BD);
    float rs = g_rsx[a] * (1.0f / AD);
    float4 q4 = *reinterpret_cast<const float4*>(g_q + i4);
    float4 g;
    g.x = rs - q4.x; g.y = rs - q4.y; g.z = rs - q4.z; g.w = rs - q4.w;
    *reinterpret_cast<float4*>(g_grad + i4) = g;
    float4 cc = make_float4(1.0f / AD, 1.0f / AD, 1.0f / AD, 1.0f / AD);
    *reinterpret_cast<float4*>(g_c + i4) = cc;
}

// =====================================================================
// fp32 SIMT GEMM (X only — full precision)
// =====================================================================
template <bool AKM, bool BKM, int SCALE>
__global__ void __launch_bounds__(256) gemm_kernel(
    const float* __restrict__ A, const float* __restrict__ B, float* __restrict__ C,
    int M, int N, int K, int lda, int ldb, int ldc, const float* __restrict__ scale)
{
    __shared__ float As[16][132];
    __shared__ float Bs[16][132];
    const int tid = threadIdx.x;
    const int tx = tid & 15, ty = tid >> 4;
    const int m0 = blockIdx.y * 128, n0 = blockIdx.x * 128;
    float acc[8][8];
#pragma unroll
    for (int i = 0; i < 8; i++)
#pragma unroll
        for (int j = 0; j < 8; j++) acc[i][j] = 0.f;

    for (int k0 = 0; k0 < K; k0 += 16) {
#pragma unroll
        for (int i = 0; i < 2; i++) {
            int lin = tid + i * 256;
            if (AKM) {
                int kk = lin >> 5, mm = (lin & 31) << 2;
                float4 v = *reinterpret_cast<const float4*>(A + (size_t)(k0 + kk) * lda + (m0 + mm));
                *reinterpret_cast<float4*>(&As[kk][mm]) = v;
            } else {
                int mm = lin >> 2, kk = (lin & 3) << 2;
                float4 v = *reinterpret_cast<const float4*>(A + (size_t)(m0 + mm) * lda + (k0 + kk));
                As[kk + 0][mm] = v.x; As[kk + 1][mm] = v.y;
                As[kk + 2][mm] = v.z; As[kk + 3][mm] = v.w;
            }
        }
#pragma unroll
        for (int i = 0; i < 2; i++) {
            int lin = tid + i * 256;
            if (BKM) {
                int kk = lin >> 5, nn = (lin & 31) << 2;
                float4 v = *reinterpret_cast<const float4*>(B + (size_t)(k0 + kk) * ldb + (n0 + nn));
                *reinterpret_cast<float4*>(&Bs[kk][nn]) = v;
            } else {
                int nn = lin >> 2, kk = (lin & 3) << 2;
                float4 v = *reinterpret_cast<const float4*>(B + (size_t)(n0 + nn) * ldb + (k0 + kk));
                Bs[kk + 0][nn] = v.x; Bs[kk + 1][nn] = v.y;
                Bs[kk + 2][nn] = v.z; Bs[kk + 3][nn] = v.w;
            }
        }
        __syncthreads();
#pragma unroll
        for (int k = 0; k < 16; k++) {
            float af[8], bf[8];
            *reinterpret_cast<float4*>(&af[0]) = *reinterpret_cast<float4*>(&As[k][ty * 8]);
            *reinterpret_cast<float4*>(&af[4]) = *reinterpret_cast<float4*>(&As[k][ty * 8 + 4]);
            *reinterpret_cast<float4*>(&bf[0]) = *reinterpret_cast<float4*>(&Bs[k][tx * 8]);
            *reinterpret_cast<float4*>(&bf[4]) = *reinterpret_cast<float4*>(&Bs[k][tx * 8 + 4]);
#pragma unroll
            for (int i = 0; i < 8; i++)
#pragma unroll
                for (int j = 0; j < 8; j++) acc[i][j] += af[i] * bf[j];
        }
        __syncthreads();
    }
#pragma unroll
    for (int i = 0; i < 8; i++) {
        int m = m0 + ty * 8 + i;
        float rowf = (SCALE == 2) ? scale[m] : 1.f;
#pragma unroll
        for (int j = 0; j < 8; j++) {
            float f = (SCALE == 1) ? scale[n0 + tx * 8 + j] : rowf;
            C[(size_t)m * ldc + n0 + tx * 8 + j] = acc[i][j] * f;
        }
    }
}

// =====================================================================
// generic tf32 mma GEMM (fragment-order operands).
// EPI=1: also emits per-CTA column partials of sum(sm*xsm), sum(c*xsm).
// =====================================================================
#define A_CH 16384
#define B_CH 16384
#define SMEM_DYN (2 * (A_CH + B_CH))

template <int SCALE, int EPI>
__global__ void __launch_bounds__(256, 2) mma_gemm_kernel(
    const float* __restrict__ Af, const float* __restrict__ Bf,
    float* __restrict__ C, int kt_tot, int nck, int ldc,
    const float* __restrict__ scale)
{
    extern __shared__ char smc[];
    const uint32_t sb = smem_u32(smc);
    const int tid = threadIdx.x;
    const int wid = tid >> 5, lane = tid & 31;
    const int m0 = blockIdx.y * 128, n0 = blockIdx.x * 128;
    const int mt0 = m0 >> 4;
    const int nt0 = n0 >> 3;

    float acc[2][8][4];
#pragma unroll
    for (int i = 0; i < 2; i++)
#pragma unroll
        for (int j = 0; j < 8; j++)
#pragma unroll
            for (int v = 0; v < 4; v++) acc[i][j][v] = 0.f;

#define PREFETCH(CK, BUF) do { \
    const int _kt0 = (CK) * 4; \
    _Pragma("unroll") \
    for (int s = 0; s < 4; s++) { \
        int idx = tid + s * 256; \
        int mtl = idx >> 7, remA = idx & 127; \
        const float* srcA = Af + ((size_t)(mt0 + mtl) * kt_tot + _kt0) * 128 + remA * 4; \
        CP16(sb + (BUF) * (A_CH + B_CH) + (mtl * 128 + remA) * 16, srcA); \
        int ntl = idx >> 6, remB = idx & 63; \
        const float* srcB = Bf + ((size_t)(nt0 + ntl) * kt_tot + _kt0) * 64 + remB * 4; \
        CP16(sb + (BUF) * (A_CH + B_CH) + A_CH + (ntl * 64 + remB) * 16, srcB); \
    } \
    CP_COMMIT(); } while (0)

    PREFETCH(0, 0);

    const int wm = (wid >> 1) * 2;
    const int wn = (wid & 1) * 8;

    for (int ck = 0; ck < nck; ck++) {
        const int buf = ck & 1;
        if (ck + 1 < nck) {
            PREFETCH(ck + 1, (ck + 1) & 1);
            CP_WAIT(1);
        } else {
            CP_WAIT(0);
        }
        __syncthreads();

        const char* Abase = smc + buf * (A_CH + B_CH);
        const char* Bbase = Abase + A_CH;

#pragma unroll
        for (int ktl = 0; ktl < 4; ktl++) {
            uint32_t afr[2][4];
#pragma unroll
            for (int i = 0; i < 2; i++) {
                uint4 v = *reinterpret_cast<const uint4*>(
                    Abase + (((wm + i) * 4 + ktl) * 32 + lane) * 16);
                afr[i][0] = v.x; afr[i][1] = v.y; afr[i][2] = v.z; afr[i][3] = v.w;
            }
            uint32_t bfr[8][2];
#pragma unroll
            for (int j = 0; j < 8; j++) {
                uint2 v = *reinterpret_cast<const uint2*>(
                    Bbase + (((wn + j) * 4 + ktl) * 32 + lane) * 8);
                bfr[j][0] = v.x; bfr[j][1] = v.y;
            }
#pragma unroll
            for (int i = 0; i < 2; i++)
#pragma unroll
                for (int j = 0; j < 8; j++)
                    mma_tf32_16n8k8(acc[i][j], afr[i], bfr[j]);
        }
        __syncthreads();
    }
#undef PREFETCH

    const int grp = lane >> 2, q4 = lane & 3;
    if (EPI) {
        __shared__ float2 s_ps[4][2][4][8];
        __shared__ float2 s_pc[4][2][4][8];
        const int rw = wid >> 1, cw = wid & 1;
#pragma unroll
        for (int j = 0; j < 8; j++) {
            float2 ps = {0.f, 0.f}, pv = {0.f, 0.f};
#pragma unroll
            for (int i = 0; i < 2; i++) {
                int row = m0 + rw * 32 + i * 16 + grp;
                int col = n0 + cw * 64 + j * 8 + q4 * 2;
                *reinterpret_cast<float2*>(C + (size_t)row * ldc + col) =
                    make_float2(acc[i][j][0], acc[i][j][1]);
                *reinterpret_cast<float2*>(C + (size_t)(row + 8) * ldc + col) =
                    make_float2(acc[i][j][2], acc[i][j][3]);
                float2 s0 = *reinterpret_cast<const float2*>(g_sm + (size_t)row * BD + col);
                float2 s1 = *reinterpret_cast<const float2*>(g_sm + (size_t)(row + 8) * BD + col);
                float2 c0 = *reinterpret_cast<const float2*>(g_c + (size_t)row * BD + col);
                float2 c1 = *reinterpret_cast<const float2*>(g_c + (size_t)(row + 8) * BD + col);
                ps.x += s0.x * acc[i][j][0] + s1.x * acc[i][j][2];
                ps.y += s0.y * acc[i][j][1] + s1.y * acc[i][j][3];
                pv.x += c0.x * acc[i][j][0] + c1.x * acc[i][j][2];
                pv.y += c0.y * acc[i][j][1] + c1.y * acc[i][j][3];
            }
#pragma unroll
            for (int o = 16; o >= 4; o >>= 1) {
                ps.x += __shfl_down_sync(0xffffffffu, ps.x, o);
                ps.y += __shfl_down_sync(0xffffffffu, ps.y, o);
                pv.x += __shfl_down_sync(0xffffffffu, pv.x, o);
                pv.y += __shfl_down_sync(0xffffffffu, pv.y, o);
            }
            if (grp == 0) { s_ps[rw][cw][q4][j] = ps; s_pc[rw][cw][q4][j] = pv; }
        }
        __syncthreads();
        if (tid < 128) {
            int cw2 = tid >> 6, rem = tid & 63;
            int j2 = rem >> 3, q2 = (rem >> 1) & 3, pr = rem & 1;
            float ss = 0.f, cc = 0.f;
#pragma unroll
            for (int r2 = 0; r2 < 4; r2++) {
                float2 a = s_ps[r2][cw2][q2][j2];
                float2 b = s_pc[r2][cw2][q2][j2];
                ss += pr ? a.y : a.x;
                cc += pr ? b.y : b.x;
            }
            int col = n0 + cw2 * 64 + j2 * 8 + q2 * 2 + pr;
            g_psm[(size_t)blockIdx.y * BD + col] = ss;
            g_pcx[(size_t)blockIdx.y * BD + col] = cc;
        }
    } else {
#pragma unroll
        for (int i = 0; i < 2; i++) {
            int row = m0 + (wid >> 1) * 32 + i * 16 + grp;
            float s0 = (SCALE == 2) ? scale[row] : 1.f;
            float s1 = (SCALE == 2) ? scale[row + 8] : 1.f;
#pragma unroll
            for (int j = 0; j < 8; j++) {
                int col = n0 + (wid & 1) * 64 + j * 8 + q4 * 2;
                *reinterpret_cast<float2*>(C + (size_t)row * ldc + col) =
                    make_float2(acc[i][j][0] * s0, acc[i][j][1] * s0);
                *reinterpret_cast<float2*>(C + (size_t)(row + 8) * ldc + col) =
                    make_float2(acc[i][j][2] * s1, acc[i][j][3] * s1);
            }
        }
    }
}

// =====================================================================
// argmin kernels
// =====================================================================
__global__ void __launch_bounds__(256) argmin_full_kernel() {
    const int a = blockIdx.x;
    const float* row = g_grad + (size_t)a * BD;
    unsigned long long best = ~0ull;
    for (int it = 0; it < 16; it++) {
        int j = threadIdx.x * 4 + it * 1024;
        float4 v = *reinterpret_cast<const float4*>(row + j);
        unsigned long long k0 = packmin(v.x, j);
        unsigned long long k1 = packmin(v.y, j + 1);
        unsigned long long k2 = packmin(v.z, j + 2);
        unsigned long long k3 = packmin(v.w, j + 3);
        if (k1 < k0) k0 = k1;
        if (k3 < k2) k2 = k3;
        if (k2 < k0) k0 = k2;
        if (k0 < best) best = k0;
    }
    __shared__ unsigned long long sk[256];
    sk[threadIdx.x] = best;
    __syncthreads();
    for (int o = 128; o; o >>= 1) {
        if (threadIdx.x < o && sk[threadIdx.x + o] < sk[threadIdx.x])
            sk[threadIdx.x] = sk[threadIdx.x + o];
        __syncthreads();
    }
    if (!threadIdx.x) g_amin[a] = (int)(sk[0] & 0xFFFFFFFFu);
}

__global__ void __launch_bounds__(256) argmin_parts_kernel() {
    const int wid = threadIdx.x >> 5, lane = threadIdx.x & 31;
    const int a = blockIdx.x * 8 + wid;
    unsigned long long best = ~0ull;
#pragma unroll
    for (int k = 0; k < NBLK / 32; k++) {
        unsigned long long v = g_minp[(size_t)a * NBLK + lane + k * 32];
        if (v < best) best = v;
    }
#pragma unroll
    for (int o = 16; o; o >>= 1) {
        unsigned long long v = __shfl_down_sync(0xffffffffu, best, o);
        if (v < best) best = v;
    }
    if (!lane) g_amin[a] = (int)(best & 0xFFFFFFFFu);
}

// =====================================================================
// selection list
// =====================================================================
__device__ __forceinline__ void build_sel_list(
    const int* amin_s, int j0, int* sel_a, int* sel_j, int* nsel_s,
    int tid)
{
    if (tid < 32) {
        int cnt = 0;
        for (int base = 0; base < AD; base += 32) {
            int a = base + tid;
            int jm = amin_s[a];
            bool mt = (jm >= j0 && jm < j0 + 64);
            unsigned mask = __ballot_sync(0xffffffffu, mt);
            if (mt) {
                int p = cnt + __popc(mask & ((1u << tid) - 1u));
                sel_a[p] = a; sel_j[p] = jm;
            }
            cnt += __popc(mask);
        }
        if (tid == 0) *nsel_s = cnt;
    }
}

// =====================================================================
// step-0 dense reduce: num_j + denom partials
// =====================================================================
__global__ void __launch_bounds__(256) nd_reduce_kernel() {
    const int tid = threadIdx.x, tx = tid & 15, ty = tid >> 4;
    const int j0 = blockIdx.x * 64, jb = j0 + tx * 4;
    __shared__ int amin_s[AD];
    __shared__ int sel_a[AD], sel_j[AD], nsel_s;
    for (int a = tid; a < AD; a += 256) amin_s[a] = g_amin[a];
    __syncthreads();
    build_sel_list(amin_s, j0, sel_a, sel_j, &nsel_s, tid);
    __syncthreads();
    const int ns = nsel_s;

    float4 num4 = {0, 0, 0, 0}, den4 = {0, 0, 0, 0};
    for (int a = ty; a < AD; a += 16) {
        size_t idx = (size_t)a * BD + jb;
        float4 cc = *reinterpret_cast<const float4*>(g_c + idx);
        float4 gg = *reinterpret_cast<const float4*>(g_grad + idx);
        float4 qq = *reinterpret_cast<const float4*>(g_q + idx);
        float4 S = {0, 0, 0, 0};
        for (int e = 0; e < ns; e++) {
            float xv = g_X[a * AD + sel_a[e]];
            int d = sel_j[e] - jb;
            S.x += (d == 0) ? xv : 0.f;
            S.y += (d == 1) ? xv : 0.f;
            S.z += (d == 2) ? xv : 0.f;
            S.w += (d == 3) ? xv : 0.f;
        }
        int am = amin_s[a];
        float4 dd, xd;
        dd.x = ((am == jb + 0) ? 1.f : 0.f) - cc.x;
        dd.y = ((am == jb + 1) ? 1.f : 0.f) - cc.y;
        dd.z = ((am == jb + 2) ? 1.f : 0.f) - cc.z;
        dd.w = ((am == jb + 3) ? 1.f : 0.f) - cc.w;
        xd.x = S.x - gg.x - qq.x; xd.y = S.y - gg.y - qq.y;
        xd.z = S.z - gg.z - qq.z; xd.w = S.w - gg.w - qq.w;
        num4.x += dd.x * gg.x; num4.y += dd.y * gg.y;
        num4.z += dd.z * gg.z; num4.w += dd.w * gg.w;
        den4.x += dd.x * xd.x; den4.y += dd.y * xd.y;
        den4.z += dd.z * xd.z; den4.w += dd.w * xd.w;
    }
    __shared__ float4 rn[16][17], rd[16][17];
    __shared__ float colden[16];
    rn[ty][tx] = num4; rd[ty][tx] = den4;
    __syncthreads();
    if (ty == 0) {
        float4 n = rn[0][tx], d = rd[0][tx];
        for (int t = 1; t < 16; t++) {
            float4 n2 = rn[t][tx], d2 = rd[t][tx];
            n.x += n2.x; n.y += n2.y; n.z += n2.z; n.w += n2.w;
            d.x += d2.x; d.y += d2.y; d.z += d2.z; d.w += d2.w;
        }
        *reinterpret_cast<float4*>(g_num + jb) = n;
        colden[tx] = d.x + d.y + d.z + d.w;
    }
    __syncthreads();
    if (tid == 0) {
        float s = 0.f;
        for (int t = 0; t < 16; t++) s += colden[t];
        g_denpart[blockIdx.x] = s;
    }
}

__global__ void __launch_bounds__(256) lam0_kernel() {
    __shared__ float red[256];
    const int tid = threadIdx.x;
    red[tid] = g_denpart[tid];
    __syncthreads();
    for (int o = 128; o; o >>= 1) {
        if (tid < o) red[tid] += red[tid + o];
        __syncthreads();
    }
    const float denom = red[0] + EPSC;
    int j = blockIdx.x * 256 + tid;
    g_lam[j] = fminf(fmaxf(-g_num[j] / denom, 0.f), 1.f);
}

// =====================================================================
// fused nondiff update (+ colcg/colcq + argmin partials)
// =====================================================================
__global__ void __launch_bounds__(256) nd_update_kernel() {
    const int tid = threadIdx.x, tx = tid & 15, ty = tid >> 4;
    const int j0 = blockIdx.x * 64, jb = j0 + tx * 4;
    __shared__ int amin_s[AD];
    __shared__ int sel_a[AD], sel_j[AD], nsel_s;
    for (int a = tid; a < AD; a += 256) amin_s[a] = g_amin[a];
    __syncthreads();
    build_sel_list(amin_s, j0, sel_a, sel_j, &nsel_s, tid);
    __syncthreads();
    const int ns = nsel_s;
    const float4 lam = *reinterpret_cast<const float4*>(g_lam + jb);

    float4 cg4 = {0, 0, 0, 0}, cq4 = {0, 0, 0, 0};
    for (int a = ty; a < AD; a += 16) {
        size_t idx = (size_t)a * BD + jb;
        float4 cc = *reinterpret_cast<const float4*>(g_c + idx);
        float4 gg = *reinterpret_cast<const float4*>(g_grad + idx);
        float4 qq = *reinterpret_cast<const float4*>(g_q + idx);
        float4 S = {0, 0, 0, 0};
        for (int e = 0; e < ns; e++) {
            float xv = g_X[a * AD + sel_a[e]];
            int d = sel_j[e] - jb;
            S.x += (d == 0) ? xv : 0.f;
            S.y += (d == 1) ? xv : 0.f;
            S.z += (d == 2) ? xv : 0.f;
            S.w += (d == 3) ? xv : 0.f;
        }
        int am = amin_s[a];
        float4 dd, xd, c2, g2;
        dd.x = ((am == jb + 0) ? 1.f : 0.f) - cc.x;
        dd.y = ((am == jb + 1) ? 1.f : 0.f) - cc.y;
        dd.z = ((am == jb + 2) ? 1.f : 0.f) - cc.z;
        dd.w = ((am == jb + 3) ? 1.f : 0.f) - cc.w;
        xd.x = S.x - gg.x - qq.x; xd.y = S.y - gg.y - qq.y;
        xd.z = S.z - gg.z - qq.z; xd.w = S.w - gg.w - qq.w;
        c2.x = cc.x + lam.x * dd.x; c2.y = cc.y + lam.y * dd.y;
        c2.z = cc.z + lam.z * dd.z; c2.w = cc.w + lam.w * dd.w;
        g2.x = gg.x + lam.x * xd.x; g2.y = gg.y + lam.y * xd.y;
        g2.z = gg.z + lam.z * xd.z; g2.w = gg.w + lam.w * xd.w;
        *reinterpret_cast<float4*>(g_c + idx)    = c2;
        *reinterpret_cast<float4*>(g_grad + idx) = g2;

        cg4.x += c2.x * g2.x; cg4.y += c2.y * g2.y;
        cg4.z += c2.z * g2.z; cg4.w += c2.w * g2.w;
        cq4.x += c2.x * qq.x; cq4.y += c2.y * qq.y;
        cq4.z += c2.z * qq.z; cq4.w += c2.w * qq.w;

        unsigned long long best = packmin(g2.x, jb);
        unsigned long long k1 = packmin(g2.y, jb + 1);
        unsigned long long k2 = packmin(g2.z, jb + 2);
        unsigned long long k3 = packmin(g2.w, jb + 3);
        if (k1 < best) best = k1;
        if (k2 < best) best = k2;
        if (k3 < best) best = k3;
#pragma unroll
        for (int o = 8; o; o >>= 1) {
            unsigned long long v = __shfl_down_sync(0xffffffffu, best, o, 16);
            if (v < best) best = v;
        }
        if (tx == 0) g_minp[(size_t)a * NBLK + blockIdx.x] = best;
    }
    __shared__ float4 rg[16][17], rq[16][17];
    rg[ty][tx] = cg4; rq[ty][tx] = cq4;
    __syncthreads();
    if (ty == 0) {
        float4 cg = rg[0][tx], cq = rq[0][tx];
        for (int t = 1; t < 16; t++) {
            float4 a2 = rg[t][tx], b2 = rq[t][tx];
            cg.x += a2.x; cg.y += a2.y; cg.z += a2.z; cg.w += a2.w;
            cq.x += b2.x; cq.y += b2.y; cq.z += b2.z; cq.w += b2.w;
        }
        *reinterpret_cast<float4*>(g_colcg + jb) = cg;
        *reinterpret_cast<float4*>(g_colcq + jb) = cq;
    }
}

// =====================================================================
// sparse num/den path (nondiff steps 1..29)
// =====================================================================
__global__ void __launch_bounds__(128) gather_kernel() {
    __shared__ int amin_s[AD];
    __shared__ float red[128];
    const int a = blockIdx.x, tid = threadIdx.x;
    for (int i = tid; i < AD; i += 128) amin_s[i] = g_amin[i];
    __syncthreads();
    const int j = amin_s[a];
    float p = 0.f;
    const float* xrow = g_X + a * AD;
    for (int ap = tid; ap < AD; ap += 128)
        if (amin_s[ap] == j) p += xrow[ap];
    red[tid] = p;
    __syncthreads();
    for (int o = 64; o; o >>= 1) {
        if (tid < o) red[tid] += red[tid + o];
        __syncthreads();
    }
    if (tid == 0) {
        g_pp[a] = red[0];
        g_gp[a] = g_grad[(size_t)a * BD + j];
        g_qp[a] = g_q[(size_t)a * BD + j];
    }
}

__global__ void __launch_bounds__(256) numden_kernel() {
    __shared__ int amin_s[AD];
    __shared__ float gp[AD], qp[AD], pp[AD];
    const int tid = threadIdx.x;
    for (int i = tid; i < AD; i += 256) {
        amin_s[i] = g_amin[i];
        gp[i] = g_gp[i]; qp[i] = g_qp[i]; pp[i] = g_pp[i];
    }
    __syncthreads();
    const int j = blockIdx.x * 256 + tid;
    float G = 0.f, Q = 0.f, P = 0.f;
    for (int e = 0; e < AD; e++) {
        bool m = (amin_s[e] == j);
        G += m ? gp[e] : 0.f;
        Q += m ? qp[e] : 0.f;
        P += m ? pp[e] : 0.f;
    }
    float ccg = g_colcg[j], ccq = g_colcq[j];
    g_num[j] = G - ccg;
    g_den[j] = P - 2.f * (G + Q) + ccg + ccq;
}

__global__ void __launch_bounds__(256) lam_kernel() {
    __shared__ float red[256];
    const int tid = threadIdx.x;
    float s = 0.f;
    for (int i = 0; i < 64; i++) s += g_den[tid * 64 + i];
    red[tid] = s;
    __syncthreads();
    for (int o = 128; o; o >>= 1) {
        if (tid < o) red[tid] += red[tid + o];
        __syncthreads();
    }
    const float denom = red[0] + EPSC;
    int j = blockIdx.x * 256 + tid;
    g_lam[j] = fminf(fmaxf(-g_num[j] / denom, 0.f), 1.f);
}

// =====================================================================
// diff phase: fused update+softmax+column-sum kernel.
// MODE 0: no update (first softmax); MODE 1: apply lam then softmax.
// Emits colcg, colcq (pass1) and colsg, colsq (pass2); writes sm + smTp.
// =====================================================================
template <int MODE>
__global__ void __launch_bounds__(256) d_fused_kernel() {
    const int tid = threadIdx.x, tx = tid & 15, ty = tid >> 4;
    const int j0 = blockIdx.x * 64, jb = j0 + tx * 4;
    float4 lam = {0, 0, 0, 0};
    if (MODE) lam = *reinterpret_cast<const float4*>(g_lam + jb);

    // pass 1: update + colcg/colcq + online softmax stats
    float4 cg4 = {0, 0, 0, 0}, cq4 = {0, 0, 0, 0};
    float4 m4 = {-INFINITY, -INFINITY, -INFINITY, -INFINITY};
    float4 s4 = {0, 0, 0, 0};
    for (int a = ty; a < AD; a += 16) {
        size_t idx = (size_t)a * BD + jb;
        float4 cc = *reinterpret_cast<const float4*>(g_c + idx);
        float4 gg = *reinterpret_cast<const float4*>(g_grad + idx);
        float4 qq = *reinterpret_cast<const float4*>(g_q + idx);
        float4 c2, g2;
        if (MODE) {
            float4 sm = *reinterpret_cast<const float4*>(g_sm + idx);
            float4 xs = *reinterpret_cast<const float4*>(g_xsm + idx);
            c2.x = cc.x + lam.x * (sm.x - cc.x);
            c2.y = cc.y + lam.y * (sm.y - cc.y);
            c2.z = cc.z + lam.z * (sm.z - cc.z);
            c2.w = cc.w + lam.w * (sm.w - cc.w);
            g2.x = gg.x + lam.x * (xs.x - gg.x - qq.x);
            g2.y = gg.y + lam.y * (xs.y - gg.y - qq.y);
            g2.z = gg.z + lam.z * (xs.z - gg.z - qq.z);
            g2.w = gg.w + lam.w * (xs.w - gg.w - qq.w);
            *reinterpret_cast<float4*>(g_c + idx)    = c2;
            *reinterpret_cast<float4*>(g_grad + idx) = g2;
        } else {
            c2 = cc; g2 = gg;
        }
        cg4.x += c2.x * g2.x; cg4.y += c2.y * g2.y;
        cg4.z += c2.z * g2.z; cg4.w += c2.w * g2.w;
        cq4.x += c2.x * qq.x; cq4.y += c2.y * qq.y;
        cq4.z += c2.z * qq.z; cq4.w += c2.w * qq.w;
        float v;
        v = -TEMPC * g2.x; if (v > m4.x) { s4.x = s4.x * expf(m4.x - v) + 1.f; m4.x = v; } else s4.x += expf(v - m4.x);
        v = -TEMPC * g2.y; if (v > m4.y) { s4.y = s4.y * expf(m4.y - v) + 1.f; m4.y = v; } else s4.y += expf(v - m4.y);
        v = -TEMPC * g2.z; if (v > m4.z) { s4.z = s4.z * expf(m4.z - v) + 1.f; m4.z = v; } else s4.z += expf(v - m4.z);
        v = -TEMPC * g2.w; if (v > m4.w) { s4.w = s4.w * expf(m4.w - v) + 1.f; m4.w = v; } else s4.w += expf(v - m4.w);
    }
    __shared__ float4 mm[16][17], ss[16][17];
    __shared__ float4 fm[16], fsinv[16];
    __shared__ float4 rg[16][17], rq[16][17];
    mm[ty][tx] = m4; ss[ty][tx] = s4;
    rg[ty][tx] = cg4; rq[ty][tx] = cq4;
    __syncthreads();
    if (ty == 0) {
        float4 M = mm[0][tx], S = ss[0][tx];
        float4 cg = rg[0][tx], cq = rq[0][tx];
        for (int t = 1; t < 16; t++) {
            float4 m2 = mm[t][tx], s2 = ss[t][tx];
            float Mn;
            Mn = fmaxf(M.x, m2.x); S.x = S.x * expf(M.x - Mn) + s2.x * expf(m2.x - Mn); M.x = Mn;
            Mn = fmaxf(M.y, m2.y); S.y = S.y * expf(M.y - Mn) + s2.y * expf(m2.y - Mn); M.y = Mn;
            Mn = fmaxf(M.z, m2.z); S.z = S.z * expf(M.z - Mn) + s2.z * expf(m2.z - Mn); M.z = Mn;
            Mn = fmaxf(M.w, m2.w); S.w = S.w * expf(M.w - Mn) + s2.w * expf(m2.w - Mn); M.w = Mn;
            float4 a2 = rg[t][tx], b2 = rq[t][tx];
            cg.x += a2.x; cg.y += a2.y; cg.z += a2.z; cg.w += a2.w;
            cq.x += b2.x; cq.y += b2.y; cq.z += b2.z; cq.w += b2.w;
        }
        fm[tx] = M;
        fsinv[tx] = make_float4(1.f / S.x, 1.f / S.y, 1.f / S.z, 1.f / S.w);
        *reinterpret_cast<float4*>(g_colcg + jb) = cg;
        *reinterpret_cast<float4*>(g_colcq + jb) = cq;
    }
    __syncthreads();
    const float4 M4 = fm[tx];
    const float4 I4 = fsinv[tx];

    // pass 2: write sm + smTp, accumulate colsg/colsq
    __shared__ float tile[32][68];
    const int L = tid & 31, nt = tid >> 5;
    float4 sg4 = {0, 0, 0, 0}, sq4 = {0, 0, 0, 0};
    for (int at = 0; at < 32; at++) {
        const int a0 = at * 32;
#pragma unroll
        for (int half = 0; half < 2; half++) {
            int aa = ty + half * 16;
            size_t idx = (size_t)(a0 + aa) * BD + jb;
            float4 g = *reinterpret_cast<const float4*>(g_grad + idx);
            float4 qq = *reinterpret_cast<const float4*>(g_q + idx);
            float4 e;
            e.x = expf(-TEMPC * g.x - M4.x) * I4.x;
            e.y = expf(-TEMPC * g.y - M4.y) * I4.y;
            e.z = expf(-TEMPC * g.z - M4.z) * I4.z;
            e.w = expf(-TEMPC * g.w - M4.w) * I4.w;
            *reinterpret_cast<float4*>(g_sm + idx) = e;
            tile[aa][tx * 4 + 0] = e.x;
            tile[aa][tx * 4 + 1] = e.y;
            tile[aa][tx * 4 + 2] = e.z;
            tile[aa][tx * 4 + 3] = e.w;
            sg4.x += e.x * g.x; sg4.y += e.y * g.y;
            sg4.z += e.z * g.z; sg4.w += e.w * g.w;
            sq4.x += e.x * qq.x; sq4.y += e.y * qq.y;
            sq4.z += e.z * qq.z; sq4.w += e.w * qq.w;
        }
        __syncthreads();
#pragma unroll
        for (int kt = 0; kt < 4; kt++) {
            float v0 = tile[kt * 8 + (L & 3)][nt * 8 + (L >> 2)];
            float v1 = tile[kt * 8 + (L & 3) + 4][nt * 8 + (L >> 2)];
            size_t o = (((size_t)(j0 / 8 + nt) * 128 + (at * 4 + kt)) * 32 + L) * 2;
            *reinterpret_cast<float2*>(g_smTp + o) =
                make_float2(tf32_rna(v0), tf32_rna(v1));
        }
        __syncthreads();
    }
    rg[ty][tx] = sg4; rq[ty][tx] = sq4;
    __syncthreads();
    if (ty == 0) {
        float4 sg = rg[0][tx], sq = rq[0][tx];
        for (int t = 1; t < 16; t++) {
            float4 a2 = rg[t][tx], b2 = rq[t][tx];
            sg.x += a2.x; sg.y += a2.y; sg.z += a2.z; sg.w += a2.w;
            sq.x += b2.x; sq.y += b2.y; sq.z += b2.z; sq.w += b2.w;
        }
        *reinterpret_cast<float4*>(g_colsg + jb) = sg;
        *reinterpret_cast<float4*>(g_colsq + jb) = sq;
    }
}

// num/den from column sums + mma epilogue partials
__global__ void __launch_bounds__(256) numden_diff_kernel() {
    const int j = blockIdx.x * 256 + threadIdx.x;
    float sxs = 0.f, cxs = 0.f;
#pragma unroll
    for (int yb = 0; yb < 8; yb++) {
        sxs += g_psm[(size_t)yb * BD + j];
        cxs += g_pcx[(size_t)yb * BD + j];
    }
    float num = g_colsg[j] - g_colcg[j];
    float den = (sxs - cxs) - num - (g_colsq[j] - g_colcq[j]);
    g_num[j] = num;
    g_den[j] = den;
}

// final diff update: c only
__global__ void __launch_bounds__(256) d_final_kernel() {
    const int tid = threadIdx.x, tx = tid & 15, ty = tid >> 4;
    const int jb = blockIdx.x * 64 + tx * 4;
    const float4 lam = *reinterpret_cast<const float4*>(g_lam + jb);
    for (int a = ty; a < AD; a += 16) {
        size_t idx = (size_t)a * BD + jb;
        float4 sm = *reinterpret_cast<const float4*>(g_sm + idx);
        float4 cc = *reinterpret_cast<const float4*>(g_c + idx);
        float4 c2;
        c2.x = cc.x + lam.x * (sm.x - cc.x);
        c2.y = cc.y + lam.y * (sm.y - cc.y);
        c2.z = cc.z + lam.z * (sm.z - cc.z);
        c2.w = cc.w + lam.w * (sm.w - cc.w);
        *reinterpret_cast<float4*>(g_c + idx) = c2;
    }
}

// =====================================================================
// host launcher
// =====================================================================
extern "C" void kernel_launch(void* const* d_in, const int* in_sizes, int n_in,
                              void* d_out, int out_size)
{
    const float* y     = (const float*)d_in[0];
    const float* atoms = (const float*)d_in[1];
    float* out = (float*)d_out;

    float *p_anorm, *p_X, *p_Xp, *p_anAp, *p_yp, *p_cTp, *p_anTp, *p_q, *p_xsm, *p_smTp, *p_ynorm;
    cudaGetSymbolAddress((void**)&p_anorm, g_anorm);
    cudaGetSymbolAddress((void**)&p_X,     g_X);
    cudaGetSymbolAddress((void**)&p_Xp,    g_Xp);
    cudaGetSymbolAddress((void**)&p_anAp,  g_anAp);
    cudaGetSymbolAddress((void**)&p_yp,    g_yp);
    cudaGetSymbolAddress((void**)&p_cTp,   g_cTp);
    cudaGetSymbolAddress((void**)&p_anTp,  g_anTp);
    cudaGetSymbolAddress((void**)&p_q,     g_q);
    cudaGetSymbolAddress((void**)&p_xsm,   g_xsm);
    cudaGetSymbolAddress((void**)&p_smTp,  g_smTp);
    cudaGetSymbolAddress((void**)&p_ynorm, g_ynorm);

    cudaFuncSetAttribute((const void*)mma_gemm_kernel<0, 0>,
                         cudaFuncAttributeMaxDynamicSharedMemorySize, SMEM_DYN);
    cudaFuncSetAttribute((const void*)mma_gemm_kernel<0, 1>,
                         cudaFuncAttributeMaxDynamicSharedMemorySize, SMEM_DYN);
    cudaFuncSetAttribute((const void*)mma_gemm_kernel<2, 0>,
                         cudaFuncAttributeMaxDynamicSharedMemorySize, SMEM_DYN);

    ynorm_kernel<<<BD / 8, 256>>>(y);
    anorm_kernel<<<AD, 256>>>(atoms);

    gemm_kernel<false, false, 0><<<dim3(AD / 128, AD / 128), 256>>>(
        p_anorm, p_anorm, p_X, AD, AD, DD, DD, DD, AD, nullptr);
    rowsumX_kernel<<<AD / 8, 256>>>();
    xperm_kernel<<<1024, 256>>>();

    anAperm_kernel<<<768, 256>>>();
    yBperm_kernel<<<24576, 256>>>(y);
    mma_gemm_kernel<0, 0><<<dim3(BD / 128, AD / 128), 256, SMEM_DYN>>>(
        p_anAp, p_yp, p_q, 96, 24, BD, nullptr);

    init_kernel<<<(AD * BD) / 1024, 256>>>();

    // nondiff phase
    argmin_full_kernel<<<AD, 256>>>();
    nd_reduce_kernel<<<NBLK, 256>>>();
    lam0_kernel<<<BD / 256, 256>>>();
    for (int s = 0; s < NONDIFF; s++) {
        nd_update_kernel<<<NBLK, 256>>>();
        if (s + 1 < NONDIFF) {
            argmin_parts_kernel<<<AD / 8, 256>>>();
            gather_kernel<<<AD, 128>>>();
            numden_kernel<<<BD / 256, 256>>>();
            lam_kernel<<<BD / 256, 256>>>();
        }
    }

    // diff phase: fused update+softmax, mma with reduction epilogue
    d_fused_kernel<0><<<NBLK, 256>>>();
    for (int s = 0; s < DIFFST; s++) {
        mma_gemm_kernel<0, 1><<<dim3(BD / 128, AD / 128), 256, SMEM_DYN>>>(
            p_Xp, p_smTp, p_xsm, 128, 32, BD, nullptr);
        numden_diff_kernel<<<BD / 256, 256>>>();
        lam_kernel<<<BD / 256, 256>>>();
        if (s + 1 < DIFFST) d_fused_kernel<1><<<NBLK, 256>>>();
        else                d_final_kernel<<<NBLK, 256>>>();
    }

    cAperm_kernel<<<16384, 256>>>();
    anBperm_kernel<<<1536, 256>>>();
    mma_gemm_kernel<2, 0><<<dim3(DD / 128, BD / 128), 256, SMEM_DYN>>>(
        p_cTp, p_anTp, out, 128, 32, DD, p_ynorm);
}